// round 3
// baseline (speedup 1.0000x reference)
#include <cuda_runtime.h>
#include <math.h>

#define NHEADS 16
#define INDIM  1024
#define DHEAD  64
#define BATCH  2
#define SEQ    2048
#define NTOK   (BATCH*SEQ)

// Scratch for projected q/k/v, layout [B*H][S][DHEAD]. 16.8 MB each.
__device__ float g_q[(size_t)BATCH*NHEADS*SEQ*DHEAD];
__device__ float g_k[(size_t)BATCH*NHEADS*SEQ*DHEAD];
__device__ float g_v[(size_t)BATCH*NHEADS*SEQ*DHEAD];

// ---------------------------------------------------------------------------
// Projection: C[m][n] = sum_k X[m][k] * W[h][k][n] + b[h][n]
// Tile 128m x 64n, BK=32, 128 threads (tx=tid&7 cols, ty=tid>>3 rows).
// Thread microtile 8x8: rows {4ty+i, 64+4ty+i}, cols {4tx+j, 32+4tx+j}.
// Grid: (NTOK/128, NHEADS, 3)   proj 0=q, 1=k, 2=v
// ---------------------------------------------------------------------------
__global__ __launch_bounds__(128)
void proj_kernel(const float* __restrict__ x,
                 const float* __restrict__ Wq, const float* __restrict__ bq,
                 const float* __restrict__ Wk, const float* __restrict__ bk,
                 const float* __restrict__ Wv, const float* __restrict__ bv)
{
    __shared__ float As[32 * 132];  // [k][m] stride 132, m<128 (transposed)
    __shared__ float Bs[32 * 68];   // [k][n] stride 68

    const int mbase = blockIdx.x * 128;
    const int h     = blockIdx.y;
    const int proj  = blockIdx.z;

    const float* W    = (proj == 0) ? Wq : (proj == 1) ? Wk : Wv;
    const float* bias = (proj == 0) ? bq : (proj == 1) ? bk : bv;
    float*       outp = (proj == 0) ? g_q : (proj == 1) ? g_k : g_v;
    W    += (size_t)h * INDIM * DHEAD;
    bias += h * DHEAD;

    const int tid = threadIdx.x;
    const int tx  = tid & 7;      // col group
    const int ty  = tid >> 3;     // row group (0..15)

    float acc[8][8];
#pragma unroll
    for (int i = 0; i < 8; i++)
#pragma unroll
        for (int j = 0; j < 8; j++) acc[i][j] = 0.f;

    for (int k0 = 0; k0 < INDIM; k0 += 32) {
        // A tile 128x32 transposed into As. Consecutive-r mapping:
        // warp lanes take consecutive rows -> conflict-free scalar STS.
#pragma unroll
        for (int it = 0; it < 8; it++) {
            int idx = tid + it * 128;       // 1024 float4 slots
            int r   = idx & 127;
            int k4  = idx >> 7;             // 0..7
            float4 a4 = *(const float4*)(x + (size_t)(mbase + r) * INDIM + k0 + (k4 << 2));
            As[((k4 << 2) + 0) * 132 + r] = a4.x;
            As[((k4 << 2) + 1) * 132 + r] = a4.y;
            As[((k4 << 2) + 2) * 132 + r] = a4.z;
            As[((k4 << 2) + 3) * 132 + r] = a4.w;
        }
        // B tile 32x64
#pragma unroll
        for (int it = 0; it < 4; it++) {
            int idx = tid + it * 128;       // 512 float4 slots
            int kb  = idx >> 4;             // 0..31
            int n4  = idx & 15;
            *(float4*)(&Bs[kb * 68 + (n4 << 2)]) =
                *(const float4*)(W + (size_t)(k0 + kb) * DHEAD + (n4 << 2));
        }
        __syncthreads();

#pragma unroll
        for (int kk = 0; kk < 32; kk++) {
            float4 alo = *(const float4*)(&As[kk * 132 + (ty << 2)]);
            float4 ahi = *(const float4*)(&As[kk * 132 + 64 + (ty << 2)]);
            float4 blo = *(const float4*)(&Bs[kk * 68 + (tx << 2)]);
            float4 bhi = *(const float4*)(&Bs[kk * 68 + 32 + (tx << 2)]);
            float a[8] = {alo.x, alo.y, alo.z, alo.w, ahi.x, ahi.y, ahi.z, ahi.w};
            float b[8] = {blo.x, blo.y, blo.z, blo.w, bhi.x, bhi.y, bhi.z, bhi.w};
#pragma unroll
            for (int i = 0; i < 8; i++)
#pragma unroll
                for (int j = 0; j < 8; j++)
                    acc[i][j] += a[i] * b[j];
        }
        __syncthreads();
    }

    float4 bl = *(const float4*)(bias + (tx << 2));
    float4 bh4 = *(const float4*)(bias + 32 + (tx << 2));
#pragma unroll
    for (int i = 0; i < 8; i++) {
        int ri = (i < 4) ? ((ty << 2) + i) : (64 + (ty << 2) + i - 4);
        int m  = mbase + ri;
        int b  = m >> 11;            // /SEQ
        int s  = m & 2047;           // %SEQ
        float* o = outp + ((size_t)(b * NHEADS + h) * SEQ + s) * DHEAD;
        *(float4*)(o + (tx << 2)) =
            make_float4(acc[i][0] + bl.x, acc[i][1] + bl.y,
                        acc[i][2] + bl.z, acc[i][3] + bl.w);
        *(float4*)(o + 32 + (tx << 2)) =
            make_float4(acc[i][4] + bh4.x, acc[i][5] + bh4.y,
                        acc[i][6] + bh4.z, acc[i][7] + bh4.w);
    }
}

// ---------------------------------------------------------------------------
// Flash attention (fp32): 64-query tile x 128-key chunks, 128 threads.
// tx=tid&15 (cols), ty=tid>>4 (0..7, rows).
// Score microtile 8x8: rows {4ty+i, 32+4ty+i}, cols {4tx+j, 64+4tx+j}.
// Output microtile 8x4: same rows, cols {4tx+j}.
// Reference: softmax FIRST, then /sqrt(64) -> epilogue scale 1/(l*8).
// SMEM: Qs[64][68] ([d][r]) | KP: Ks[64][132] ([d][c]) aliased by
//       Ps[128][68] ([c][r]) | Vs[128][64] ([c][v]).
// ---------------------------------------------------------------------------
#define QS_FLOATS (64 * 68)
#define KP_FLOATS (128 * 68)     // 8704 >= 64*132 = 8448
#define VS_FLOATS (128 * 64)
#define ATTN_SMEM_BYTES ((QS_FLOATS + KP_FLOATS + VS_FLOATS) * 4)

__global__ __launch_bounds__(128)
void attn_kernel(float* __restrict__ out)
{
    extern __shared__ float sm[];
    float* Qs = sm;                       // [d][r] stride 68
    float* KP = sm + QS_FLOATS;           // Ks: [d][c] stride 132 / Ps: [c][r] stride 68
    float* Vs = sm + QS_FLOATS + KP_FLOATS; // [c][v] stride 64

    const int qbase = blockIdx.x * 64;
    const int bh    = blockIdx.y;
    const float* Q = g_q + (size_t)bh * SEQ * DHEAD;
    const float* K = g_k + (size_t)bh * SEQ * DHEAD;
    const float* V = g_v + (size_t)bh * SEQ * DHEAD;

    const int tid = threadIdx.x;
    const int tx  = tid & 15;
    const int ty  = tid >> 4;    // 0..7

    // Load Q tile 64x64 transposed: Qs[d][r]. Consecutive-r lanes -> clean STS.
#pragma unroll
    for (int it = 0; it < 8; it++) {
        int idx = tid + it * 128;          // 1024 float4 slots
        int r   = idx & 63;
        int d4  = (idx >> 6) & 15;
        float4 a4 = *(const float4*)(Q + (size_t)(qbase + r) * DHEAD + (d4 << 2));
        Qs[((d4 << 2) + 0) * 68 + r] = a4.x;
        Qs[((d4 << 2) + 1) * 68 + r] = a4.y;
        Qs[((d4 << 2) + 2) * 68 + r] = a4.z;
        Qs[((d4 << 2) + 3) * 68 + r] = a4.w;
    }

    float m[8], l[8], acc[8][4];
#pragma unroll
    for (int i = 0; i < 8; i++) {
        m[i] = -1e30f; l[i] = 0.f;
#pragma unroll
        for (int j = 0; j < 4; j++) acc[i][j] = 0.f;
    }

    for (int kb = 0; kb < SEQ; kb += 128) {
        __syncthreads();   // prior PV readers of KP/Vs done (iter 0: Q stores)

        // K chunk 128x64 transposed -> KP as Ks[d][c] stride 132
#pragma unroll
        for (int it = 0; it < 16; it++) {
            int idx = tid + it * 128;      // 2048 float4 slots
            int r   = idx & 127;
            int d4  = idx >> 7;            // 0..15
            float4 k4 = *(const float4*)(K + (size_t)(kb + r) * DHEAD + (d4 << 2));
            KP[((d4 << 2) + 0) * 132 + r] = k4.x;
            KP[((d4 << 2) + 1) * 132 + r] = k4.y;
            KP[((d4 << 2) + 2) * 132 + r] = k4.z;
            KP[((d4 << 2) + 3) * 132 + r] = k4.w;
        }
        // V chunk 128x64 natural
#pragma unroll
        for (int it = 0; it < 16; it++) {
            int idx = tid + it * 128;
            int d4  = idx & 15;
            int r   = idx >> 4;            // 0..127
            *(float4*)(&Vs[r * 64 + (d4 << 2)]) =
                *(const float4*)(V + (size_t)(kb + r) * DHEAD + (d4 << 2));
        }
        __syncthreads();

        // QK^T: s[i][j] over 64 dims
        float s[8][8];
#pragma unroll
        for (int i = 0; i < 8; i++)
#pragma unroll
            for (int j = 0; j < 8; j++) s[i][j] = 0.f;

#pragma unroll 4
        for (int d = 0; d < 64; d++) {
            float4 qlo = *(const float4*)(&Qs[d * 68 + (ty << 2)]);
            float4 qhi = *(const float4*)(&Qs[d * 68 + 32 + (ty << 2)]);
            float4 klo = *(const float4*)(&KP[d * 132 + (tx << 2)]);
            float4 khi = *(const float4*)(&KP[d * 132 + 64 + (tx << 2)]);
            float qa[8] = {qlo.x, qlo.y, qlo.z, qlo.w, qhi.x, qhi.y, qhi.z, qhi.w};
            float ka[8] = {klo.x, klo.y, klo.z, klo.w, khi.x, khi.y, khi.z, khi.w};
#pragma unroll
            for (int i = 0; i < 8; i++)
#pragma unroll
                for (int j = 0; j < 8; j++)
                    s[i][j] += qa[i] * ka[j];
        }

        // Online softmax. Row threads (fixed ty, tx 0..15) share a 16-lane
        // half-warp (lane = (ty&1)*16 + tx) -> shfl_xor offsets < 16 stay in-row.
#pragma unroll
        for (int i = 0; i < 8; i++) {
            float mx = s[i][0];
#pragma unroll
            for (int j = 1; j < 8; j++) mx = fmaxf(mx, s[i][j]);
#pragma unroll
            for (int off = 1; off < 16; off <<= 1)
                mx = fmaxf(mx, __shfl_xor_sync(0xffffffffu, mx, off));
            float mnew  = fmaxf(m[i], mx);
            float alpha = __expf(m[i] - mnew);
            float ps = 0.f;
#pragma unroll
            for (int j = 0; j < 8; j++) { s[i][j] = __expf(s[i][j] - mnew); ps += s[i][j]; }
#pragma unroll
            for (int off = 1; off < 16; off <<= 1)
                ps += __shfl_xor_sync(0xffffffffu, ps, off);
            l[i] = l[i] * alpha + ps;
            m[i] = mnew;
#pragma unroll
            for (int j = 0; j < 4; j++) acc[i][j] *= alpha;
        }

        __syncthreads();   // all QK reads of Ks done before P overwrites KP

        // Store P transposed: Ps[c][r] stride 68, float4 over row groups
#pragma unroll
        for (int j = 0; j < 8; j++) {
            int c = (j < 4) ? ((tx << 2) + j) : (64 + (tx << 2) + j - 4);
            *(float4*)(&KP[c * 68 + (ty << 2)]) =
                make_float4(s[0][j], s[1][j], s[2][j], s[3][j]);
            *(float4*)(&KP[c * 68 + 32 + (ty << 2)]) =
                make_float4(s[4][j], s[5][j], s[6][j], s[7][j]);
        }
        __syncthreads();

        // PV: acc[i][j] += P[ri][c] * V[c][4tx+j]
#pragma unroll 4
        for (int c = 0; c < 128; c++) {
            float4 plo = *(const float4*)(&KP[c * 68 + (ty << 2)]);
            float4 phi = *(const float4*)(&KP[c * 68 + 32 + (ty << 2)]);
            float4 v4  = *(const float4*)(&Vs[c * 64 + (tx << 2)]);
            float pa[8] = {plo.x, plo.y, plo.z, plo.w, phi.x, phi.y, phi.z, phi.w};
            float va[4] = {v4.x, v4.y, v4.z, v4.w};
#pragma unroll
            for (int i = 0; i < 8; i++)
#pragma unroll
                for (int j = 0; j < 4; j++)
                    acc[i][j] += pa[i] * va[j];
        }
    }

    // Epilogue: out[b][s][h*64 + v] = acc / (l * sqrt(64))
    const int b = bh >> 4, h = bh & 15;
#pragma unroll
    for (int i = 0; i < 8; i++) {
        int ri  = (i < 4) ? ((ty << 2) + i) : (32 + (ty << 2) + i - 4);
        float inv = 1.0f / (l[i] * 8.0f);
        int srow = qbase + ri;
        float* o = out + ((size_t)(b * SEQ + srow)) * (NHEADS * DHEAD) + h * DHEAD + (tx << 2);
        *(float4*)o = make_float4(acc[i][0] * inv, acc[i][1] * inv,
                                  acc[i][2] * inv, acc[i][3] * inv);
    }
}

// ---------------------------------------------------------------------------
extern "C" void kernel_launch(void* const* d_in, const int* in_sizes, int n_in,
                              void* d_out, int out_size)
{
    const float* x  = (const float*)d_in[0];
    const float* Wq = (const float*)d_in[1];
    const float* bq = (const float*)d_in[2];
    const float* Wk = (const float*)d_in[3];
    const float* bk = (const float*)d_in[4];
    const float* Wv = (const float*)d_in[5];
    const float* bv = (const float*)d_in[6];
    float* out = (float*)d_out;

    static int configured = 0;
    if (!configured) {
        cudaFuncSetAttribute(attn_kernel,
                             cudaFuncAttributeMaxDynamicSharedMemorySize,
                             ATTN_SMEM_BYTES);
        configured = 1;
    }

    proj_kernel<<<dim3(NTOK / 128, NHEADS, 3), 128>>>(x, Wq, bq, Wk, bk, Wv, bv);
    attn_kernel<<<dim3(SEQ / 64, BATCH * NHEADS), 128, ATTN_SMEM_BYTES>>>(out);
}

// round 7
// speedup vs baseline: 1.3561x; 1.3561x over previous
#include <cuda_runtime.h>
#include <cuda_bf16.h>
#include <stdint.h>
#include <math.h>

#define NHEADS 16
#define INDIM  1024
#define DHEAD  64
#define BATCH  2
#define SEQ    2048
#define NTOK   (BATCH*SEQ)

// fp32 q/k/v scratch, layout [B*H][S][DHEAD]
__device__ float g_q[(size_t)BATCH*NHEADS*SEQ*DHEAD];
__device__ float g_k[(size_t)BATCH*NHEADS*SEQ*DHEAD];
__device__ float g_v[(size_t)BATCH*NHEADS*SEQ*DHEAD];

// Split-precision inputs for bf16 tensor-core MMA (raw u16 payloads).
// x: [tok][k] hi/lo.  Wt: [h*3+p][n][k] hi/lo (pre-transposed).
__device__ unsigned short g_xhi[(size_t)NTOK*INDIM];
__device__ unsigned short g_xlo[(size_t)NTOK*INDIM];
__device__ unsigned short g_wthi[(size_t)NHEADS*3*DHEAD*INDIM];
__device__ unsigned short g_wtlo[(size_t)NHEADS*3*DHEAD*INDIM];

__device__ __forceinline__ uint32_t smem_u32(const void* p) {
    uint32_t a;
    asm("{ .reg .u64 t; cvta.to.shared.u64 t, %1; cvt.u32.u64 %0, t; }"
        : "=r"(a) : "l"(p));
    return a;
}

__device__ __forceinline__ unsigned short f2bf_hi(float f) {
    __nv_bfloat16 h = __float2bfloat16(f);
    __nv_bfloat16_raw r = *(__nv_bfloat16_raw*)&h;
    return r.x;
}
__device__ __forceinline__ float bf2f(unsigned short u) {
    __nv_bfloat16_raw r; r.x = u;
    __nv_bfloat16 h = *(__nv_bfloat16*)&r;
    return __bfloat162float(h);
}

// bf16 mma: D(f32) = A(bf16,row) x B(bf16,col) + C, m16n8k16. Canonical form.
__device__ __forceinline__ void mma_bf16(float* c, const uint32_t* a,
                                         const uint32_t* b) {
    float d0, d1, d2, d3;
    asm volatile(
        "mma.sync.aligned.m16n8k16.row.col.f32.bf16.bf16.f32 "
        "{%0,%1,%2,%3}, {%4,%5,%6,%7}, {%8,%9}, {%10,%11,%12,%13};"
        : "=f"(d0), "=f"(d1), "=f"(d2), "=f"(d3)
        : "r"(a[0]), "r"(a[1]), "r"(a[2]), "r"(a[3]),
          "r"(b[0]), "r"(b[1]),
          "f"(c[0]), "f"(c[1]), "f"(c[2]), "f"(c[3]));
    c[0] = d0; c[1] = d1; c[2] = d2; c[3] = d3;
}

#define LDMATRIX_X4(r0, r1, r2, r3, addr)                                      \
    asm volatile("ldmatrix.sync.aligned.m8n8.x4.shared.b16 {%0,%1,%2,%3}, [%4];" \
                 : "=r"(r0), "=r"(r1), "=r"(r2), "=r"(r3) : "r"(addr))

// ---------------------------------------------------------------------------
// convert_x: x fp32 -> bf16 hi + bf16 lo. One thread = one float4.
// ---------------------------------------------------------------------------
__global__ __launch_bounds__(256)
void convert_x(const float* __restrict__ x)
{
    int i = blockIdx.x * 256 + threadIdx.x;   // float4 index
    float4 v = ((const float4*)x)[i];
    float f[4] = {v.x, v.y, v.z, v.w};
    ushort4 hh, ll;
    unsigned short* hp = (unsigned short*)&hh;
    unsigned short* lp = (unsigned short*)&ll;
#pragma unroll
    for (int j = 0; j < 4; j++) {
        unsigned short hu = f2bf_hi(f[j]);
        unsigned short lu = f2bf_hi(f[j] - bf2f(hu));
        hp[j] = hu; lp[j] = lu;
    }
    ((ushort4*)g_xhi)[i] = hh;
    ((ushort4*)g_xlo)[i] = ll;
}

// ---------------------------------------------------------------------------
// convert_w: W[h][k][n] fp32 -> Wt[h*3+p][n][k] bf16 hi/lo (tile transpose).
// Grid: (INDIM/64, NHEADS*3), 256 threads.
// ---------------------------------------------------------------------------
__global__ __launch_bounds__(256)
void convert_w(const float* __restrict__ Wq, const float* __restrict__ Wk,
               const float* __restrict__ Wv)
{
    __shared__ float tile[64][65];
    const int k0 = blockIdx.x * 64;
    const int hp = blockIdx.y;            // h*3 + p
    const int h  = hp / 3, p = hp % 3;
    const float* W = ((p == 0) ? Wq : (p == 1) ? Wk : Wv) + (size_t)h * INDIM * DHEAD;
    const int tid = threadIdx.x;

#pragma unroll
    for (int it = 0; it < 16; it++) {
        int idx = tid + it * 256;
        int kk = idx >> 6, n = idx & 63;
        tile[kk][n] = W[(size_t)(k0 + kk) * DHEAD + n];
    }
    __syncthreads();
#pragma unroll
    for (int it = 0; it < 16; it++) {
        int idx = tid + it * 256;
        int n = idx >> 6, kk = idx & 63;
        float v = tile[kk][n];
        unsigned short hu = f2bf_hi(v);
        unsigned short lu = f2bf_hi(v - bf2f(hu));
        size_t o = (size_t)hp * DHEAD * INDIM + (size_t)n * INDIM + k0 + kk;
        g_wthi[o] = hu; g_wtlo[o] = lu;
    }
}

// ---------------------------------------------------------------------------
// proj_mma: bf16-split projection on tensor cores (mma.sync m16n8k16).
// Grid (NTOK/128, NHEADS, 3), 128 threads = 4 warps. CTA: 128 tokens x 64 out.
// Warp w: rows [w*32, w*32+32). C = Xhi*Whi + Xhi*Wlo + Xlo*Whi, fp32 accum.
// SMEM rows padded to 72 elems (144B): ldmatrix stride 144 % 128 = 16 ->
// conflict-free 8-row phases.
// ---------------------------------------------------------------------------
#define AHI_OFF 0
#define ALO_OFF (128*72)
#define BHI_OFF (2*128*72)
#define BLO_OFF (2*128*72 + 64*72)
#define PROJ_SMEM_ELEMS (2*128*72 + 2*64*72)   // u16 elems = 27648 (55296 B)

__global__ __launch_bounds__(128)
void proj_mma(const float* __restrict__ bq, const float* __restrict__ bk,
              const float* __restrict__ bv)
{
    extern __shared__ char smem_raw[];
    unsigned short* sb = (unsigned short*)smem_raw;
    const uint32_t sbase = smem_u32(sb);

    const int tid  = threadIdx.x;
    const int wid  = tid >> 5;
    const int lane = tid & 31;
    const int mbase = blockIdx.x * 128;
    const int h     = blockIdx.y;
    const int p     = blockIdx.z;

    const unsigned short* Whi = g_wthi + (size_t)(h * 3 + p) * DHEAD * INDIM;
    const unsigned short* Wlo = g_wtlo + (size_t)(h * 3 + p) * DHEAD * INDIM;

    float acc[2][8][4];
#pragma unroll
    for (int mt = 0; mt < 2; mt++)
#pragma unroll
        for (int nt = 0; nt < 8; nt++)
#pragma unroll
            for (int e = 0; e < 4; e++) acc[mt][nt][e] = 0.f;

    // ldmatrix lane-address decodes (constant per thread)
    const int mi   = lane >> 3;        // matrix index 0..3
    const int l8   = lane & 7;
    // A x4: m = base + l8 + (mi&1)*8, k = k0 + (mi>>1)*8
    const int a_rofs = l8 + (mi & 1) * 8;
    const int a_kofs = (mi >> 1) * 8;
    // B x4 (two n-tiles): n = n0 + l8 + (mi>>1)*8, k = k0 + (mi&1)*8
    const int b_nofs = l8 + (mi >> 1) * 8;
    const int b_kofs = (mi & 1) * 8;

    for (int c = 0; c < 16; c++) {
        __syncthreads();   // prior-iteration ldmatrix reads done
        // ---- A hi/lo: 128 rows x 64 elems each (8 uint4 segs per row) ----
#pragma unroll
        for (int it = 0; it < 8; it++) {
            int idx = tid + it * 128;        // 1024 slots
            int r = idx >> 3, sg = idx & 7;
            *(uint4*)(sb + AHI_OFF + r * 72 + sg * 8) =
                *(const uint4*)(g_xhi + (size_t)(mbase + r) * INDIM + c * 64 + sg * 8);
            *(uint4*)(sb + ALO_OFF + r * 72 + sg * 8) =
                *(const uint4*)(g_xlo + (size_t)(mbase + r) * INDIM + c * 64 + sg * 8);
        }
        // ---- B hi/lo: 64 rows x 64 elems ----
#pragma unroll
        for (int it = 0; it < 4; it++) {
            int idx = tid + it * 128;        // 512 slots
            int n = idx >> 3, sg = idx & 7;
            *(uint4*)(sb + BHI_OFF + n * 72 + sg * 8) =
                *(const uint4*)(Whi + (size_t)n * INDIM + c * 64 + sg * 8);
            *(uint4*)(sb + BLO_OFF + n * 72 + sg * 8) =
                *(const uint4*)(Wlo + (size_t)n * INDIM + c * 64 + sg * 8);
        }
        __syncthreads();

#pragma unroll
        for (int ks = 0; ks < 4; ks++) {
            const int k0 = ks * 16;
            // B fragments: 8 n-tiles, hi and lo (4 x4-loads each)
            uint32_t bhi[8][2], blo[8][2];
#pragma unroll
            for (int np = 0; np < 4; np++) {
                int n = np * 16 + b_nofs;
                uint32_t ah = sbase + (uint32_t)(BHI_OFF + n * 72 + k0 + b_kofs) * 2;
                uint32_t al = sbase + (uint32_t)(BLO_OFF + n * 72 + k0 + b_kofs) * 2;
                LDMATRIX_X4(bhi[np*2][0], bhi[np*2][1], bhi[np*2+1][0], bhi[np*2+1][1], ah);
                LDMATRIX_X4(blo[np*2][0], blo[np*2][1], blo[np*2+1][0], blo[np*2+1][1], al);
            }
#pragma unroll
            for (int mt = 0; mt < 2; mt++) {
                int r = wid * 32 + mt * 16 + a_rofs;
                uint32_t ahad = sbase + (uint32_t)(AHI_OFF + r * 72 + k0 + a_kofs) * 2;
                uint32_t alad = sbase + (uint32_t)(ALO_OFF + r * 72 + k0 + a_kofs) * 2;
                uint32_t ah[4], al[4];
                LDMATRIX_X4(ah[0], ah[1], ah[2], ah[3], ahad);
                LDMATRIX_X4(al[0], al[1], al[2], al[3], alad);
#pragma unroll
                for (int nt = 0; nt < 8; nt++) {
                    mma_bf16(acc[mt][nt], ah, bhi[nt]);   // hi*hi
                    mma_bf16(acc[mt][nt], ah, blo[nt]);   // hi*lo
                    mma_bf16(acc[mt][nt], al, bhi[nt]);   // lo*hi
                }
            }
        }
    }

    // ---- epilogue: fragments -> g_q/g_k/g_v with bias ----
    const float* bias = ((p == 0) ? bq : (p == 1) ? bk : bv) + h * DHEAD;
    float* outp = (p == 0) ? g_q : (p == 1) ? g_k : g_v;
    const int quad = lane >> 2, pr = lane & 3;

#pragma unroll
    for (int mt = 0; mt < 2; mt++) {
#pragma unroll
        for (int half = 0; half < 2; half++) {     // c0c1 (row) / c2c3 (row+8)
            int tok = mbase + wid * 32 + mt * 16 + quad + half * 8;
            int b = tok >> 11, s = tok & 2047;
            float* dst = outp + ((size_t)(b * NHEADS + h) * SEQ + s) * DHEAD;
#pragma unroll
            for (int nt = 0; nt < 8; nt++) {
                int col = nt * 8 + pr * 2;
                float2 bb = *(const float2*)(bias + col);
                float2 v;
                v.x = acc[mt][nt][half * 2 + 0] + bb.x;
                v.y = acc[mt][nt][half * 2 + 1] + bb.y;
                *(float2*)(dst + col) = v;
            }
        }
    }
}

// ---------------------------------------------------------------------------
// Flash attention (fp32) — round-2 version (measured 1079us), unchanged.
// ---------------------------------------------------------------------------
#define PAD 68
#define ATTN_SMEM_BYTES ((2*64*PAD + 64*64) * 4)

__global__ __launch_bounds__(256)
void attn_kernel(float* __restrict__ out)
{
    extern __shared__ char smem_raw[];
    float* smf = (float*)smem_raw;
    float* Qs = smf;
    float* Ks = smf + 64 * PAD;
    float* Vs = smf + 2 * 64 * PAD;

    const int qbase = blockIdx.x * 64;
    const int bh    = blockIdx.y;
    const float* Q = g_q + (size_t)bh * SEQ * DHEAD;
    const float* K = g_k + (size_t)bh * SEQ * DHEAD;
    const float* V = g_v + (size_t)bh * SEQ * DHEAD;

    const int tid = threadIdx.x;
    const int tx  = tid & 15;
    const int ty  = tid >> 4;

#pragma unroll
    for (int it = 0; it < 4; it++) {
        int idx = tid + it * 256;
        int r   = idx >> 4;
        int d   = (idx & 15) << 2;
        float4 a4 = *(const float4*)(Q + (size_t)(qbase + r) * DHEAD + d);
        Qs[(d + 0) * PAD + r] = a4.x; Qs[(d + 1) * PAD + r] = a4.y;
        Qs[(d + 2) * PAD + r] = a4.z; Qs[(d + 3) * PAD + r] = a4.w;
    }

    float m[4], l[4], acc[4][4];
#pragma unroll
    for (int i = 0; i < 4; i++) {
        m[i] = -1e30f; l[i] = 0.f;
#pragma unroll
        for (int j = 0; j < 4; j++) acc[i][j] = 0.f;
    }

    for (int kb = 0; kb < SEQ; kb += 64) {
        __syncthreads();
#pragma unroll
        for (int it = 0; it < 4; it++) {
            int idx = tid + it * 256;
            int r   = idx >> 4;
            int d   = (idx & 15) << 2;
            float4 k4 = *(const float4*)(K + (size_t)(kb + r) * DHEAD + d);
            Ks[(d + 0) * PAD + r] = k4.x; Ks[(d + 1) * PAD + r] = k4.y;
            Ks[(d + 2) * PAD + r] = k4.z; Ks[(d + 3) * PAD + r] = k4.w;
            *(float4*)(&Vs[r * 64 + d]) = *(const float4*)(V + (size_t)(kb + r) * DHEAD + d);
        }
        __syncthreads();

        float s[4][4];
#pragma unroll
        for (int i = 0; i < 4; i++)
#pragma unroll
            for (int j = 0; j < 4; j++) s[i][j] = 0.f;

#pragma unroll 8
        for (int d = 0; d < 64; d++) {
            float4 q4 = *(const float4*)(&Qs[d * PAD + (ty << 2)]);
            float4 k4 = *(const float4*)(&Ks[d * PAD + (tx << 2)]);
            float qa[4] = {q4.x, q4.y, q4.z, q4.w};
            float ka[4] = {k4.x, k4.y, k4.z, k4.w};
#pragma unroll
            for (int i = 0; i < 4; i++)
#pragma unroll
                for (int j = 0; j < 4; j++)
                    s[i][j] += qa[i] * ka[j];
        }

#pragma unroll
        for (int i = 0; i < 4; i++) {
            float mx = fmaxf(fmaxf(s[i][0], s[i][1]), fmaxf(s[i][2], s[i][3]));
#pragma unroll
            for (int off = 1; off < 16; off <<= 1)
                mx = fmaxf(mx, __shfl_xor_sync(0xffffffffu, mx, off));
            float mnew  = fmaxf(m[i], mx);
            float alpha = __expf(m[i] - mnew);
            float ps = 0.f;
#pragma unroll
            for (int j = 0; j < 4; j++) { s[i][j] = __expf(s[i][j] - mnew); ps += s[i][j]; }
#pragma unroll
            for (int off = 1; off < 16; off <<= 1)
                ps += __shfl_xor_sync(0xffffffffu, ps, off);
            l[i] = l[i] * alpha + ps;
            m[i] = mnew;
#pragma unroll
            for (int j = 0; j < 4; j++) acc[i][j] *= alpha;
        }

        __syncthreads();
#pragma unroll
        for (int i = 0; i < 4; i++)
#pragma unroll
            for (int j = 0; j < 4; j++)
                Ks[((tx << 2) + j) * PAD + (ty << 2) + i] = s[i][j];
        __syncthreads();

#pragma unroll 8
        for (int c = 0; c < 64; c++) {
            float4 p4 = *(const float4*)(&Ks[c * PAD + (ty << 2)]);
            float4 v4 = *(const float4*)(&Vs[c * 64 + (tx << 2)]);
            float pa[4] = {p4.x, p4.y, p4.z, p4.w};
            float va[4] = {v4.x, v4.y, v4.z, v4.w};
#pragma unroll
            for (int i = 0; i < 4; i++)
#pragma unroll
                for (int j = 0; j < 4; j++)
                    acc[i][j] += pa[i] * va[j];
        }
    }

    const int b = bh >> 4, h = bh & 15;
#pragma unroll
    for (int i = 0; i < 4; i++) {
        float inv  = 1.0f / (l[i] * 8.0f);
        int   srow = qbase + (ty << 2) + i;
        float* o = out + ((size_t)(b * SEQ + srow)) * (NHEADS * DHEAD) + h * DHEAD + (tx << 2);
        *(float4*)o = make_float4(acc[i][0] * inv, acc[i][1] * inv,
                                  acc[i][2] * inv, acc[i][3] * inv);
    }
}

// ---------------------------------------------------------------------------
extern "C" void kernel_launch(void* const* d_in, const int* in_sizes, int n_in,
                              void* d_out, int out_size)
{
    const float* x  = (const float*)d_in[0];
    const float* Wq = (const float*)d_in[1];
    const float* bq = (const float*)d_in[2];
    const float* Wk = (const float*)d_in[3];
    const float* bk = (const float*)d_in[4];
    const float* Wv = (const float*)d_in[5];
    const float* bv = (const float*)d_in[6];
    float* out = (float*)d_out;

    cudaFuncSetAttribute(proj_mma, cudaFuncAttributeMaxDynamicSharedMemorySize,
                         PROJ_SMEM_ELEMS * 2);
    cudaFuncSetAttribute(attn_kernel, cudaFuncAttributeMaxDynamicSharedMemorySize,
                         ATTN_SMEM_BYTES);

    convert_x<<<(NTOK * INDIM / 4) / 256, 256>>>(x);
    convert_w<<<dim3(INDIM / 64, NHEADS * 3), 256>>>(Wq, Wk, Wv);
    proj_mma<<<dim3(NTOK / 128, NHEADS, 3), 128, PROJ_SMEM_ELEMS * 2>>>(bq, bk, bv);
    attn_kernel<<<dim3(SEQ / 64, BATCH * NHEADS), 256, ATTN_SMEM_BYTES>>>(out);
}

// round 8
// speedup vs baseline: 2.7923x; 2.0590x over previous
#include <cuda_runtime.h>
#include <cuda_bf16.h>
#include <stdint.h>
#include <math.h>

#define NHEADS 16
#define INDIM  1024
#define DHEAD  64
#define BATCH  2
#define SEQ    2048
#define NTOK   (BATCH*SEQ)
#define BH     (BATCH*NHEADS)

// fp32 q/k/v scratch, layout [B*H][S][DHEAD]
__device__ float g_q[(size_t)BH*SEQ*DHEAD];
__device__ float g_k[(size_t)BH*SEQ*DHEAD];
__device__ float g_v[(size_t)BH*SEQ*DHEAD];

// Split-precision inputs for bf16 tensor-core MMA (raw u16 payloads).
__device__ unsigned short g_xhi[(size_t)NTOK*INDIM];
__device__ unsigned short g_xlo[(size_t)NTOK*INDIM];
__device__ unsigned short g_wthi[(size_t)NHEADS*3*DHEAD*INDIM];
__device__ unsigned short g_wtlo[(size_t)NHEADS*3*DHEAD*INDIM];

// Split q/k ([bh][s][d]) and transposed v ([bh][d][s]) for attention MMA.
__device__ unsigned short g_qhi[(size_t)BH*SEQ*DHEAD];
__device__ unsigned short g_qlo[(size_t)BH*SEQ*DHEAD];
__device__ unsigned short g_khi[(size_t)BH*SEQ*DHEAD];
__device__ unsigned short g_klo[(size_t)BH*SEQ*DHEAD];
__device__ unsigned short g_vthi[(size_t)BH*DHEAD*SEQ];
__device__ unsigned short g_vtlo[(size_t)BH*DHEAD*SEQ];

__device__ __forceinline__ uint32_t smem_u32(const void* p) {
    uint32_t a;
    asm("{ .reg .u64 t; cvta.to.shared.u64 t, %1; cvt.u32.u64 %0, t; }"
        : "=r"(a) : "l"(p));
    return a;
}

__device__ __forceinline__ unsigned short f2bf_hi(float f) {
    __nv_bfloat16 h = __float2bfloat16(f);
    __nv_bfloat16_raw r = *(__nv_bfloat16_raw*)&h;
    return r.x;
}
__device__ __forceinline__ float bf2f(unsigned short u) {
    return __uint_as_float((uint32_t)u << 16);
}

// split (x,y) -> bf16 hi-pair and bf16 residual-pair (lower 16 bits = x)
__device__ __forceinline__ void split_pack2(float x, float y,
                                            uint32_t& hi, uint32_t& lo) {
    unsigned short hx = f2bf_hi(x), hy = f2bf_hi(y);
    float rx = x - bf2f(hx);
    float ry = y - bf2f(hy);
    hi = (uint32_t)hx | ((uint32_t)hy << 16);
    lo = (uint32_t)f2bf_hi(rx) | ((uint32_t)f2bf_hi(ry) << 16);
}

// bf16 mma: D(f32) = A(bf16,row) x B(bf16,col) + C, m16n8k16.
__device__ __forceinline__ void mma_bf16(float* c, const uint32_t* a,
                                         const uint32_t* b) {
    float d0, d1, d2, d3;
    asm volatile(
        "mma.sync.aligned.m16n8k16.row.col.f32.bf16.bf16.f32 "
        "{%0,%1,%2,%3}, {%4,%5,%6,%7}, {%8,%9}, {%10,%11,%12,%13};"
        : "=f"(d0), "=f"(d1), "=f"(d2), "=f"(d3)
        : "r"(a[0]), "r"(a[1]), "r"(a[2]), "r"(a[3]),
          "r"(b[0]), "r"(b[1]),
          "f"(c[0]), "f"(c[1]), "f"(c[2]), "f"(c[3]));
    c[0] = d0; c[1] = d1; c[2] = d2; c[3] = d3;
}

#define LDMATRIX_X4(r0, r1, r2, r3, addr)                                      \
    asm volatile("ldmatrix.sync.aligned.m8n8.x4.shared.b16 {%0,%1,%2,%3}, [%4];" \
                 : "=r"(r0), "=r"(r1), "=r"(r2), "=r"(r3) : "r"(addr))

// ---------------------------------------------------------------------------
__global__ __launch_bounds__(256)
void convert_x(const float* __restrict__ x)
{
    int i = blockIdx.x * 256 + threadIdx.x;
    float4 v = ((const float4*)x)[i];
    float f[4] = {v.x, v.y, v.z, v.w};
    ushort4 hh, ll;
    unsigned short* hp = (unsigned short*)&hh;
    unsigned short* lp = (unsigned short*)&ll;
#pragma unroll
    for (int j = 0; j < 4; j++) {
        unsigned short hu = f2bf_hi(f[j]);
        hp[j] = hu; lp[j] = f2bf_hi(f[j] - bf2f(hu));
    }
    ((ushort4*)g_xhi)[i] = hh;
    ((ushort4*)g_xlo)[i] = ll;
}

// ---------------------------------------------------------------------------
__global__ __launch_bounds__(256)
void convert_w(const float* __restrict__ Wq, const float* __restrict__ Wk,
               const float* __restrict__ Wv)
{
    __shared__ float tile[64][65];
    const int k0 = blockIdx.x * 64;
    const int hp = blockIdx.y;
    const int h  = hp / 3, p = hp % 3;
    const float* W = ((p == 0) ? Wq : (p == 1) ? Wk : Wv) + (size_t)h * INDIM * DHEAD;
    const int tid = threadIdx.x;

#pragma unroll
    for (int it = 0; it < 16; it++) {
        int idx = tid + it * 256;
        int kk = idx >> 6, n = idx & 63;
        tile[kk][n] = W[(size_t)(k0 + kk) * DHEAD + n];
    }
    __syncthreads();
#pragma unroll
    for (int it = 0; it < 16; it++) {
        int idx = tid + it * 256;
        int n = idx >> 6, kk = idx & 63;
        float v = tile[kk][n];
        unsigned short hu = f2bf_hi(v);
        size_t o = (size_t)hp * DHEAD * INDIM + (size_t)n * INDIM + k0 + kk;
        g_wthi[o] = hu; g_wtlo[o] = f2bf_hi(v - bf2f(hu));
    }
}

// ---------------------------------------------------------------------------
// proj_mma (validated round 7, unchanged)
// ---------------------------------------------------------------------------
#define AHI_OFF 0
#define ALO_OFF (128*72)
#define BHI_OFF (2*128*72)
#define BLO_OFF (2*128*72 + 64*72)
#define PROJ_SMEM_ELEMS (2*128*72 + 2*64*72)

__global__ __launch_bounds__(128)
void proj_mma(const float* __restrict__ bq, const float* __restrict__ bk,
              const float* __restrict__ bv)
{
    extern __shared__ char smem_raw[];
    unsigned short* sb = (unsigned short*)smem_raw;
    const uint32_t sbase = smem_u32(sb);

    const int tid  = threadIdx.x;
    const int wid  = tid >> 5;
    const int lane = tid & 31;
    const int mbase = blockIdx.x * 128;
    const int h     = blockIdx.y;
    const int p     = blockIdx.z;

    const unsigned short* Whi = g_wthi + (size_t)(h * 3 + p) * DHEAD * INDIM;
    const unsigned short* Wlo = g_wtlo + (size_t)(h * 3 + p) * DHEAD * INDIM;

    float acc[2][8][4];
#pragma unroll
    for (int mt = 0; mt < 2; mt++)
#pragma unroll
        for (int nt = 0; nt < 8; nt++)
#pragma unroll
            for (int e = 0; e < 4; e++) acc[mt][nt][e] = 0.f;

    const int mi   = lane >> 3;
    const int l8   = lane & 7;
    const int a_rofs = l8 + (mi & 1) * 8;
    const int a_kofs = (mi >> 1) * 8;
    const int b_nofs = l8 + (mi >> 1) * 8;
    const int b_kofs = (mi & 1) * 8;

    for (int c = 0; c < 16; c++) {
        __syncthreads();
#pragma unroll
        for (int it = 0; it < 8; it++) {
            int idx = tid + it * 128;
            int r = idx >> 3, sg = idx & 7;
            *(uint4*)(sb + AHI_OFF + r * 72 + sg * 8) =
                *(const uint4*)(g_xhi + (size_t)(mbase + r) * INDIM + c * 64 + sg * 8);
            *(uint4*)(sb + ALO_OFF + r * 72 + sg * 8) =
                *(const uint4*)(g_xlo + (size_t)(mbase + r) * INDIM + c * 64 + sg * 8);
        }
#pragma unroll
        for (int it = 0; it < 4; it++) {
            int idx = tid + it * 128;
            int n = idx >> 3, sg = idx & 7;
            *(uint4*)(sb + BHI_OFF + n * 72 + sg * 8) =
                *(const uint4*)(Whi + (size_t)n * INDIM + c * 64 + sg * 8);
            *(uint4*)(sb + BLO_OFF + n * 72 + sg * 8) =
                *(const uint4*)(Wlo + (size_t)n * INDIM + c * 64 + sg * 8);
        }
        __syncthreads();

#pragma unroll
        for (int ks = 0; ks < 4; ks++) {
            const int k0 = ks * 16;
            uint32_t bhi[8][2], blo[8][2];
#pragma unroll
            for (int np = 0; np < 4; np++) {
                int n = np * 16 + b_nofs;
                uint32_t ah = sbase + (uint32_t)(BHI_OFF + n * 72 + k0 + b_kofs) * 2;
                uint32_t al = sbase + (uint32_t)(BLO_OFF + n * 72 + k0 + b_kofs) * 2;
                LDMATRIX_X4(bhi[np*2][0], bhi[np*2][1], bhi[np*2+1][0], bhi[np*2+1][1], ah);
                LDMATRIX_X4(blo[np*2][0], blo[np*2][1], blo[np*2+1][0], blo[np*2+1][1], al);
            }
#pragma unroll
            for (int mt = 0; mt < 2; mt++) {
                int r = wid * 32 + mt * 16 + a_rofs;
                uint32_t ahad = sbase + (uint32_t)(AHI_OFF + r * 72 + k0 + a_kofs) * 2;
                uint32_t alad = sbase + (uint32_t)(ALO_OFF + r * 72 + k0 + a_kofs) * 2;
                uint32_t ah[4], al[4];
                LDMATRIX_X4(ah[0], ah[1], ah[2], ah[3], ahad);
                LDMATRIX_X4(al[0], al[1], al[2], al[3], alad);
#pragma unroll
                for (int nt = 0; nt < 8; nt++) {
                    mma_bf16(acc[mt][nt], ah, bhi[nt]);
                    mma_bf16(acc[mt][nt], ah, blo[nt]);
                    mma_bf16(acc[mt][nt], al, bhi[nt]);
                }
            }
        }
    }

    const float* bias = ((p == 0) ? bq : (p == 1) ? bk : bv) + h * DHEAD;
    float* outp = (p == 0) ? g_q : (p == 1) ? g_k : g_v;
    const int quad = lane >> 2, pr = lane & 3;

#pragma unroll
    for (int mt = 0; mt < 2; mt++) {
#pragma unroll
        for (int half = 0; half < 2; half++) {
            int tok = mbase + wid * 32 + mt * 16 + quad + half * 8;
            int b = tok >> 11, s = tok & 2047;
            float* dst = outp + ((size_t)(b * NHEADS + h) * SEQ + s) * DHEAD;
#pragma unroll
            for (int nt = 0; nt < 8; nt++) {
                int col = nt * 8 + pr * 2;
                float2 bb = *(const float2*)(bias + col);
                float2 v;
                v.x = acc[mt][nt][half * 2 + 0] + bb.x;
                v.y = acc[mt][nt][half * 2 + 1] + bb.y;
                *(float2*)(dst + col) = v;
            }
        }
    }
}

// ---------------------------------------------------------------------------
__global__ __launch_bounds__(256)
void convert_qk()
{
    int i = blockIdx.x * 256 + threadIdx.x;     // float4 index
    const float* src = blockIdx.y ? g_k : g_q;
    unsigned short* dhi = blockIdx.y ? g_khi : g_qhi;
    unsigned short* dlo = blockIdx.y ? g_klo : g_qlo;
    float4 v = ((const float4*)src)[i];
    float f[4] = {v.x, v.y, v.z, v.w};
    ushort4 hh, ll;
    unsigned short* hp = (unsigned short*)&hh;
    unsigned short* lp = (unsigned short*)&ll;
#pragma unroll
    for (int j = 0; j < 4; j++) {
        unsigned short hu = f2bf_hi(f[j]);
        hp[j] = hu; lp[j] = f2bf_hi(f[j] - bf2f(hu));
    }
    ((ushort4*)dhi)[i] = hh;
    ((ushort4*)dlo)[i] = ll;
}

// ---------------------------------------------------------------------------
__global__ __launch_bounds__(256)
void convert_vt()
{
    __shared__ float tile[64][65];
    const int s0 = blockIdx.x * 64;
    const int bh = blockIdx.y;
    const int tid = threadIdx.x;
    const float* V = g_v + (size_t)bh * SEQ * DHEAD;

#pragma unroll
    for (int it = 0; it < 16; it++) {
        int idx = tid + it * 256;
        int r = idx >> 6, d = idx & 63;
        tile[r][d] = V[(size_t)(s0 + r) * DHEAD + d];
    }
    __syncthreads();
#pragma unroll
    for (int it = 0; it < 16; it++) {
        int idx = tid + it * 256;
        int d = idx >> 6, cc = idx & 63;
        float v = tile[cc][d];
        unsigned short hu = f2bf_hi(v);
        size_t o = (size_t)bh * DHEAD * SEQ + (size_t)d * SEQ + s0 + cc;
        g_vthi[o] = hu; g_vtlo[o] = f2bf_hi(v - bf2f(hu));
    }
}

// ---------------------------------------------------------------------------
// attn_mma: flash attention on tensor cores, bf16 3-term split QK^T and PV.
// P fragments built IN REGISTERS from QK^T C fragments (layout identity).
// ---------------------------------------------------------------------------
#define T_QHI 0
#define T_QLO (64*72)
#define T_KHI (2*64*72)
#define T_KLO (3*64*72)
#define T_VHI (4*64*72)
#define T_VLO (5*64*72)
#define ATTN_SMEM_BYTES (6*64*72*2)     // 55296

__global__ __launch_bounds__(128)
void attn_mma(float* __restrict__ out)
{
    extern __shared__ char smem_raw[];
    unsigned short* sb = (unsigned short*)smem_raw;
    const uint32_t sbase = smem_u32(sb);

    const int tid  = threadIdx.x;
    const int wq   = tid >> 5;
    const int lane = tid & 31;
    const int quad = lane >> 2, pr = lane & 3;
    const int mi   = lane >> 3, l8 = lane & 7;
    const int a_rofs = l8 + (mi & 1) * 8;
    const int a_kofs = (mi >> 1) * 8;
    const int b_nofs = l8 + (mi >> 1) * 8;
    const int b_kofs = (mi & 1) * 8;

    const int qbase = blockIdx.x * 64;
    const int bh    = blockIdx.y;

    const unsigned short* Qhi = g_qhi + (size_t)bh * SEQ * DHEAD;
    const unsigned short* Qlo = g_qlo + (size_t)bh * SEQ * DHEAD;
    const unsigned short* Khi = g_khi + (size_t)bh * SEQ * DHEAD;
    const unsigned short* Klo = g_klo + (size_t)bh * SEQ * DHEAD;
    const unsigned short* Vthi = g_vthi + (size_t)bh * DHEAD * SEQ;
    const unsigned short* Vtlo = g_vtlo + (size_t)bh * DHEAD * SEQ;

    // Load Q tile (64 rows x 64 d, hi+lo): 1024 uint4 slots
#pragma unroll
    for (int it = 0; it < 8; it++) {
        int idx  = tid + it * 128;
        int half = idx >> 9;
        int rem  = idx & 511;
        int r    = rem >> 3, sg = rem & 7;
        const unsigned short* src = half ? Qlo : Qhi;
        *(uint4*)(sb + (half ? T_QLO : T_QHI) + r * 72 + sg * 8) =
            *(const uint4*)(src + (size_t)(qbase + r) * DHEAD + sg * 8);
    }

    float oacc[8][4];
    float mrow[2] = {-1e30f, -1e30f}, lrow[2] = {0.f, 0.f};
#pragma unroll
    for (int nt = 0; nt < 8; nt++)
#pragma unroll
        for (int e = 0; e < 4; e++) oacc[nt][e] = 0.f;

    for (int kb = 0; kb < SEQ; kb += 64) {
        __syncthreads();   // previous chunk's ldmatrix reads done (iter0: Q store)
        // K hi/lo ([key][d]) tiles: 1024 uint4 slots
#pragma unroll
        for (int it = 0; it < 8; it++) {
            int idx  = tid + it * 128;
            int half = idx >> 9;
            int rem  = idx & 511;
            int r    = rem >> 3, sg = rem & 7;
            const unsigned short* src = half ? Klo : Khi;
            *(uint4*)(sb + (half ? T_KLO : T_KHI) + r * 72 + sg * 8) =
                *(const uint4*)(src + (size_t)(kb + r) * DHEAD + sg * 8);
        }
        // Vt hi/lo ([dv][key]) tiles: 1024 uint4 slots
#pragma unroll
        for (int it = 0; it < 8; it++) {
            int idx  = tid + it * 128;
            int half = idx >> 9;
            int rem  = idx & 511;
            int r    = rem >> 3, sg = rem & 7;     // r = dv row
            const unsigned short* src = half ? Vtlo : Vthi;
            *(uint4*)(sb + (half ? T_VLO : T_VHI) + r * 72 + sg * 8) =
                *(const uint4*)(src + (size_t)r * SEQ + kb + sg * 8);
        }
        __syncthreads();

        // ---- QK^T ----
        float c[8][4];
#pragma unroll
        for (int nt = 0; nt < 8; nt++)
#pragma unroll
            for (int e = 0; e < 4; e++) c[nt][e] = 0.f;

#pragma unroll
        for (int ks = 0; ks < 4; ks++) {
            const int k0 = ks * 16;
            uint32_t qh[4], ql[4];
            {
                int r = wq * 16 + a_rofs;
                LDMATRIX_X4(qh[0], qh[1], qh[2], qh[3],
                            sbase + (uint32_t)(T_QHI + r * 72 + k0 + a_kofs) * 2);
                LDMATRIX_X4(ql[0], ql[1], ql[2], ql[3],
                            sbase + (uint32_t)(T_QLO + r * 72 + k0 + a_kofs) * 2);
            }
#pragma unroll
            for (int np = 0; np < 4; np++) {
                int n = np * 16 + b_nofs;
                uint32_t kh[4], kl[4];
                LDMATRIX_X4(kh[0], kh[1], kh[2], kh[3],
                            sbase + (uint32_t)(T_KHI + n * 72 + k0 + b_kofs) * 2);
                LDMATRIX_X4(kl[0], kl[1], kl[2], kl[3],
                            sbase + (uint32_t)(T_KLO + n * 72 + k0 + b_kofs) * 2);
                uint32_t b0h[2] = {kh[0], kh[1]}, b1h[2] = {kh[2], kh[3]};
                uint32_t b0l[2] = {kl[0], kl[1]}, b1l[2] = {kl[2], kl[3]};
                mma_bf16(c[np*2],   qh, b0h);
                mma_bf16(c[np*2],   qh, b0l);
                mma_bf16(c[np*2],   ql, b0h);
                mma_bf16(c[np*2+1], qh, b1h);
                mma_bf16(c[np*2+1], qh, b1l);
                mma_bf16(c[np*2+1], ql, b1h);
            }
        }

        // ---- online softmax (rows quad / quad+8; 4 lanes per row) ----
#pragma unroll
        for (int r = 0; r < 2; r++) {
            const int e = r * 2;
            float mx = c[0][e];
#pragma unroll
            for (int nt = 0; nt < 8; nt++)
                mx = fmaxf(mx, fmaxf(c[nt][e], c[nt][e+1]));
            mx = fmaxf(mx, __shfl_xor_sync(0xffffffffu, mx, 1));
            mx = fmaxf(mx, __shfl_xor_sync(0xffffffffu, mx, 2));
            float mnew  = fmaxf(mrow[r], mx);
            float alpha = __expf(mrow[r] - mnew);
            float ps = 0.f;
#pragma unroll
            for (int nt = 0; nt < 8; nt++) {
                c[nt][e]   = __expf(c[nt][e]   - mnew);
                c[nt][e+1] = __expf(c[nt][e+1] - mnew);
                ps += c[nt][e] + c[nt][e+1];
            }
            ps += __shfl_xor_sync(0xffffffffu, ps, 1);
            ps += __shfl_xor_sync(0xffffffffu, ps, 2);
            lrow[r] = lrow[r] * alpha + ps;
            mrow[r] = mnew;
#pragma unroll
            for (int nt = 0; nt < 8; nt++) {
                oacc[nt][e]   *= alpha;
                oacc[nt][e+1] *= alpha;
            }
        }

        // ---- PV: P fragments straight from C fragments ----
#pragma unroll
        for (int ks = 0; ks < 4; ks++) {
            uint32_t ph[4], pl[4];
            split_pack2(c[2*ks][0],   c[2*ks][1],   ph[0], pl[0]);
            split_pack2(c[2*ks][2],   c[2*ks][3],   ph[1], pl[1]);
            split_pack2(c[2*ks+1][0], c[2*ks+1][1], ph[2], pl[2]);
            split_pack2(c[2*ks+1][2], c[2*ks+1][3], ph[3], pl[3]);
#pragma unroll
            for (int np = 0; np < 4; np++) {
                int n = np * 16 + b_nofs;
                uint32_t vh[4], vl[4];
                LDMATRIX_X4(vh[0], vh[1], vh[2], vh[3],
                            sbase + (uint32_t)(T_VHI + n * 72 + ks * 16 + b_kofs) * 2);
                LDMATRIX_X4(vl[0], vl[1], vl[2], vl[3],
                            sbase + (uint32_t)(T_VLO + n * 72 + ks * 16 + b_kofs) * 2);
                uint32_t b0h[2] = {vh[0], vh[1]}, b1h[2] = {vh[2], vh[3]};
                uint32_t b0l[2] = {vl[0], vl[1]}, b1l[2] = {vl[2], vl[3]};
                mma_bf16(oacc[np*2],   ph, b0h);
                mma_bf16(oacc[np*2],   ph, b0l);
                mma_bf16(oacc[np*2],   pl, b0h);
                mma_bf16(oacc[np*2+1], ph, b1h);
                mma_bf16(oacc[np*2+1], ph, b1l);
                mma_bf16(oacc[np*2+1], pl, b1h);
            }
        }
    }

    // ---- epilogue: out[b][s][h*64+dv] = oacc / (l * 8) ----
    const int b = bh >> 4, h = bh & 15;
#pragma unroll
    for (int half = 0; half < 2; half++) {
        int srow = qbase + wq * 16 + quad + half * 8;
        float inv = 1.0f / (lrow[half] * 8.0f);
        float* dst = out + ((size_t)(b * SEQ + srow)) * (NHEADS * DHEAD) + h * DHEAD;
#pragma unroll
        for (int nt = 0; nt < 8; nt++) {
            int col = nt * 8 + pr * 2;
            float2 v;
            v.x = oacc[nt][half*2 + 0] * inv;
            v.y = oacc[nt][half*2 + 1] * inv;
            *(float2*)(dst + col) = v;
        }
    }
}

// ---------------------------------------------------------------------------
extern "C" void kernel_launch(void* const* d_in, const int* in_sizes, int n_in,
                              void* d_out, int out_size)
{
    const float* x  = (const float*)d_in[0];
    const float* Wq = (const float*)d_in[1];
    const float* bq = (const float*)d_in[2];
    const float* Wk = (const float*)d_in[3];
    const float* bk = (const float*)d_in[4];
    const float* Wv = (const float*)d_in[5];
    const float* bv = (const float*)d_in[6];
    float* out = (float*)d_out;

    cudaFuncSetAttribute(proj_mma, cudaFuncAttributeMaxDynamicSharedMemorySize,
                         PROJ_SMEM_ELEMS * 2);
    cudaFuncSetAttribute(attn_mma, cudaFuncAttributeMaxDynamicSharedMemorySize,
                         ATTN_SMEM_BYTES);

    convert_x<<<(NTOK * INDIM / 4) / 256, 256>>>(x);
    convert_w<<<dim3(INDIM / 64, NHEADS * 3), 256>>>(Wq, Wk, Wv);
    proj_mma<<<dim3(NTOK / 128, NHEADS, 3), 128, PROJ_SMEM_ELEMS * 2>>>(bq, bk, bv);
    convert_qk<<<dim3((BH * SEQ * DHEAD / 4) / 256, 2), 256>>>();
    convert_vt<<<dim3(SEQ / 64, BH), 256>>>();
    attn_mma<<<dim3(SEQ / 64, BH), 128, ATTN_SMEM_BYTES>>>(out);
}

// round 10
// speedup vs baseline: 2.8593x; 1.0240x over previous
#include <cuda_runtime.h>
#include <cuda_bf16.h>
#include <stdint.h>
#include <math.h>

#define NHEADS 16
#define INDIM  1024
#define DHEAD  64
#define BATCH  2
#define SEQ    2048
#define NTOK   (BATCH*SEQ)
#define BH     (BATCH*NHEADS)

// fp32 V scratch (needed for the transpose pass), layout [B*H][S][DHEAD]
__device__ float g_v[(size_t)BH*SEQ*DHEAD];

// Split-precision inputs for bf16 tensor-core MMA (raw u16 payloads).
__device__ unsigned short g_xhi[(size_t)NTOK*INDIM];
__device__ unsigned short g_xlo[(size_t)NTOK*INDIM];
__device__ unsigned short g_wthi[(size_t)NHEADS*3*DHEAD*INDIM];
__device__ unsigned short g_wtlo[(size_t)NHEADS*3*DHEAD*INDIM];

// Split q/k ([bh][s][d]) and transposed v ([bh][d][s]) for attention MMA.
__device__ unsigned short g_qhi[(size_t)BH*SEQ*DHEAD];
__device__ unsigned short g_qlo[(size_t)BH*SEQ*DHEAD];
__device__ unsigned short g_khi[(size_t)BH*SEQ*DHEAD];
__device__ unsigned short g_klo[(size_t)BH*SEQ*DHEAD];
__device__ unsigned short g_vthi[(size_t)BH*DHEAD*SEQ];
__device__ unsigned short g_vtlo[(size_t)BH*DHEAD*SEQ];

__device__ __forceinline__ uint32_t smem_u32(const void* p) {
    uint32_t a;
    asm("{ .reg .u64 t; cvta.to.shared.u64 t, %1; cvt.u32.u64 %0, t; }"
        : "=r"(a) : "l"(p));
    return a;
}

__device__ __forceinline__ unsigned short f2bf_hi(float f) {
    __nv_bfloat16 h = __float2bfloat16(f);
    __nv_bfloat16_raw r = *(__nv_bfloat16_raw*)&h;
    return r.x;
}
__device__ __forceinline__ float bf2f(unsigned short u) {
    return __uint_as_float((uint32_t)u << 16);
}

// split (x,y) -> bf16 hi-pair and bf16 residual-pair (lower 16 bits = x)
__device__ __forceinline__ void split_pack2(float x, float y,
                                            uint32_t& hi, uint32_t& lo) {
    unsigned short hx = f2bf_hi(x), hy = f2bf_hi(y);
    float rx = x - bf2f(hx);
    float ry = y - bf2f(hy);
    hi = (uint32_t)hx | ((uint32_t)hy << 16);
    lo = (uint32_t)f2bf_hi(rx) | ((uint32_t)f2bf_hi(ry) << 16);
}

// bf16 mma: D(f32) = A(bf16,row) x B(bf16,col) + C, m16n8k16.
__device__ __forceinline__ void mma_bf16(float* c, const uint32_t* a,
                                         const uint32_t* b) {
    float d0, d1, d2, d3;
    asm volatile(
        "mma.sync.aligned.m16n8k16.row.col.f32.bf16.bf16.f32 "
        "{%0,%1,%2,%3}, {%4,%5,%6,%7}, {%8,%9}, {%10,%11,%12,%13};"
        : "=f"(d0), "=f"(d1), "=f"(d2), "=f"(d3)
        : "r"(a[0]), "r"(a[1]), "r"(a[2]), "r"(a[3]),
          "r"(b[0]), "r"(b[1]),
          "f"(c[0]), "f"(c[1]), "f"(c[2]), "f"(c[3]));
    c[0] = d0; c[1] = d1; c[2] = d2; c[3] = d3;
}

#define LDMATRIX_X4(r0, r1, r2, r3, addr)                                      \
    asm volatile("ldmatrix.sync.aligned.m8n8.x4.shared.b16 {%0,%1,%2,%3}, [%4];" \
                 : "=r"(r0), "=r"(r1), "=r"(r2), "=r"(r3) : "r"(addr))

#define CP_ASYNC16(smem_addr, gptr)                                            \
    asm volatile("cp.async.cg.shared.global [%0], [%1], 16;"                   \
                 :: "r"(smem_addr), "l"(gptr) : "memory")
#define CP_COMMIT()  asm volatile("cp.async.commit_group;" ::: "memory")
#define CP_WAIT0()   asm volatile("cp.async.wait_group 0;" ::: "memory")

// ---------------------------------------------------------------------------
__global__ __launch_bounds__(256)
void convert_x(const float* __restrict__ x)
{
    int i = blockIdx.x * 256 + threadIdx.x;
    float4 v = ((const float4*)x)[i];
    float f[4] = {v.x, v.y, v.z, v.w};
    ushort4 hh, ll;
    unsigned short* hp = (unsigned short*)&hh;
    unsigned short* lp = (unsigned short*)&ll;
#pragma unroll
    for (int j = 0; j < 4; j++) {
        unsigned short hu = f2bf_hi(f[j]);
        hp[j] = hu; lp[j] = f2bf_hi(f[j] - bf2f(hu));
    }
    ((ushort4*)g_xhi)[i] = hh;
    ((ushort4*)g_xlo)[i] = ll;
}

// ---------------------------------------------------------------------------
__global__ __launch_bounds__(256)
void convert_w(const float* __restrict__ Wq, const float* __restrict__ Wk,
               const float* __restrict__ Wv)
{
    __shared__ float tile[64][65];
    const int k0 = blockIdx.x * 64;
    const int hp = blockIdx.y;
    const int h  = hp / 3, p = hp % 3;
    const float* W = ((p == 0) ? Wq : (p == 1) ? Wk : Wv) + (size_t)h * INDIM * DHEAD;
    const int tid = threadIdx.x;

#pragma unroll
    for (int it = 0; it < 16; it++) {
        int idx = tid + it * 256;
        int kk = idx >> 6, n = idx & 63;
        tile[kk][n] = W[(size_t)(k0 + kk) * DHEAD + n];
    }
    __syncthreads();
#pragma unroll
    for (int it = 0; it < 16; it++) {
        int idx = tid + it * 256;
        int n = idx >> 6, kk = idx & 63;
        float v = tile[kk][n];
        unsigned short hu = f2bf_hi(v);
        size_t o = (size_t)hp * DHEAD * INDIM + (size_t)n * INDIM + k0 + kk;
        g_wthi[o] = hu; g_wtlo[o] = f2bf_hi(v - bf2f(hu));
    }
}

// ---------------------------------------------------------------------------
// proj_mma: validated round-7 compute; epilogue writes q/k as SPLIT hi/lo
// (packed u32 per 2 cols) directly, v as fp32 (transposed+split later).
// ---------------------------------------------------------------------------
#define AHI_OFF 0
#define ALO_OFF (128*72)
#define BHI_OFF (2*128*72)
#define BLO_OFF (2*128*72 + 64*72)
#define PROJ_SMEM_ELEMS (2*128*72 + 2*64*72)

__global__ __launch_bounds__(128)
void proj_mma(const float* __restrict__ bq, const float* __restrict__ bk,
              const float* __restrict__ bv)
{
    extern __shared__ char smem_raw[];
    unsigned short* sb = (unsigned short*)smem_raw;
    const uint32_t sbase = smem_u32(sb);

    const int tid  = threadIdx.x;
    const int wid  = tid >> 5;
    const int lane = tid & 31;
    const int mbase = blockIdx.x * 128;
    const int h     = blockIdx.y;
    const int p     = blockIdx.z;

    const unsigned short* Whi = g_wthi + (size_t)(h * 3 + p) * DHEAD * INDIM;
    const unsigned short* Wlo = g_wtlo + (size_t)(h * 3 + p) * DHEAD * INDIM;

    float acc[2][8][4];
#pragma unroll
    for (int mt = 0; mt < 2; mt++)
#pragma unroll
        for (int nt = 0; nt < 8; nt++)
#pragma unroll
            for (int e = 0; e < 4; e++) acc[mt][nt][e] = 0.f;

    const int mi   = lane >> 3;
    const int l8   = lane & 7;
    const int a_rofs = l8 + (mi & 1) * 8;
    const int a_kofs = (mi >> 1) * 8;
    const int b_nofs = l8 + (mi >> 1) * 8;
    const int b_kofs = (mi & 1) * 8;

    for (int c = 0; c < 16; c++) {
        __syncthreads();
#pragma unroll
        for (int it = 0; it < 8; it++) {
            int idx = tid + it * 128;
            int r = idx >> 3, sg = idx & 7;
            *(uint4*)(sb + AHI_OFF + r * 72 + sg * 8) =
                *(const uint4*)(g_xhi + (size_t)(mbase + r) * INDIM + c * 64 + sg * 8);
            *(uint4*)(sb + ALO_OFF + r * 72 + sg * 8) =
                *(const uint4*)(g_xlo + (size_t)(mbase + r) * INDIM + c * 64 + sg * 8);
        }
#pragma unroll
        for (int it = 0; it < 4; it++) {
            int idx = tid + it * 128;
            int n = idx >> 3, sg = idx & 7;
            *(uint4*)(sb + BHI_OFF + n * 72 + sg * 8) =
                *(const uint4*)(Whi + (size_t)n * INDIM + c * 64 + sg * 8);
            *(uint4*)(sb + BLO_OFF + n * 72 + sg * 8) =
                *(const uint4*)(Wlo + (size_t)n * INDIM + c * 64 + sg * 8);
        }
        __syncthreads();

#pragma unroll
        for (int ks = 0; ks < 4; ks++) {
            const int k0 = ks * 16;
            uint32_t bhi[8][2], blo[8][2];
#pragma unroll
            for (int np = 0; np < 4; np++) {
                int n = np * 16 + b_nofs;
                uint32_t ah = sbase + (uint32_t)(BHI_OFF + n * 72 + k0 + b_kofs) * 2;
                uint32_t al = sbase + (uint32_t)(BLO_OFF + n * 72 + k0 + b_kofs) * 2;
                LDMATRIX_X4(bhi[np*2][0], bhi[np*2][1], bhi[np*2+1][0], bhi[np*2+1][1], ah);
                LDMATRIX_X4(blo[np*2][0], blo[np*2][1], blo[np*2+1][0], blo[np*2+1][1], al);
            }
#pragma unroll
            for (int mt = 0; mt < 2; mt++) {
                int r = wid * 32 + mt * 16 + a_rofs;
                uint32_t ahad = sbase + (uint32_t)(AHI_OFF + r * 72 + k0 + a_kofs) * 2;
                uint32_t alad = sbase + (uint32_t)(ALO_OFF + r * 72 + k0 + a_kofs) * 2;
                uint32_t ah[4], al[4];
                LDMATRIX_X4(ah[0], ah[1], ah[2], ah[3], ahad);
                LDMATRIX_X4(al[0], al[1], al[2], al[3], alad);
#pragma unroll
                for (int nt = 0; nt < 8; nt++) {
                    mma_bf16(acc[mt][nt], ah, bhi[nt]);
                    mma_bf16(acc[mt][nt], ah, blo[nt]);
                    mma_bf16(acc[mt][nt], al, bhi[nt]);
                }
            }
        }
    }

    const float* bias = ((p == 0) ? bq : (p == 1) ? bk : bv) + h * DHEAD;
    const int quad = lane >> 2, pr = lane & 3;

#pragma unroll
    for (int mt = 0; mt < 2; mt++) {
#pragma unroll
        for (int half = 0; half < 2; half++) {
            int tok = mbase + wid * 32 + mt * 16 + quad + half * 8;
            int b = tok >> 11, s = tok & 2047;
            size_t base = ((size_t)(b * NHEADS + h) * SEQ + s) * DHEAD;
            if (p < 2) {
                unsigned short* dhi = p ? g_khi : g_qhi;
                unsigned short* dlo = p ? g_klo : g_qlo;
#pragma unroll
                for (int nt = 0; nt < 8; nt++) {
                    int col = nt * 8 + pr * 2;
                    float2 bb = *(const float2*)(bias + col);
                    uint32_t ph, pl;
                    split_pack2(acc[mt][nt][half*2 + 0] + bb.x,
                                acc[mt][nt][half*2 + 1] + bb.y, ph, pl);
                    *(uint32_t*)(dhi + base + col) = ph;
                    *(uint32_t*)(dlo + base + col) = pl;
                }
            } else {
                float* dst = g_v + base;
#pragma unroll
                for (int nt = 0; nt < 8; nt++) {
                    int col = nt * 8 + pr * 2;
                    float2 bb = *(const float2*)(bias + col);
                    float2 v;
                    v.x = acc[mt][nt][half*2 + 0] + bb.x;
                    v.y = acc[mt][nt][half*2 + 1] + bb.y;
                    *(float2*)(dst + col) = v;
                }
            }
        }
    }
}

// ---------------------------------------------------------------------------
__global__ __launch_bounds__(256)
void convert_vt()
{
    __shared__ float tile[64][65];
    const int s0 = blockIdx.x * 64;
    const int bh = blockIdx.y;
    const int tid = threadIdx.x;
    const float* V = g_v + (size_t)bh * SEQ * DHEAD;

#pragma unroll
    for (int it = 0; it < 16; it++) {
        int idx = tid + it * 256;
        int r = idx >> 6, d = idx & 63;
        tile[r][d] = V[(size_t)(s0 + r) * DHEAD + d];
    }
    __syncthreads();
#pragma unroll
    for (int it = 0; it < 16; it++) {
        int idx = tid + it * 256;
        int d = idx >> 6, cc = idx & 63;
        float v = tile[cc][d];
        unsigned short hu = f2bf_hi(v);
        size_t o = (size_t)bh * DHEAD * SEQ + (size_t)d * SEQ + s0 + cc;
        g_vthi[o] = hu; g_vtlo[o] = f2bf_hi(v - bf2f(hu));
    }
}

// ---------------------------------------------------------------------------
// attn_mma: bf16-split flash attention; K/V tiles via cp.async 2-stage ring.
// Per chunk: wait_group 0 -> barrier -> issue next chunk -> compute.
// The barrier proves all reads of chunk i-1 (resident in buf^1) finished
// before its overwrite begins, so 2 stages are sufficient.
// SMEM (u16): Q hi/lo [64x72]x2 | 2 x (K hi/lo + Vt hi/lo, each 64x72).
// ---------------------------------------------------------------------------
#define TQ_HI 0
#define TQ_LO 4608            // 64*72
#define BUF0  9216            // 2*64*72
#define BUFSZ 18432           // 4*64*72
#define ATTN_SMEM_BYTES ((2*4608 + 2*BUFSZ) * 2)   // 92160 B

// Issue async copies for one 64-key chunk into buffer at u16 offset `bufbase`.
// Plain function (no lambda): tid selects this thread's 16 uint4 slots.
__device__ __forceinline__ void attn_load_chunk(
    uint32_t sbase, int tid, int kb, int bufbase,
    const unsigned short* Khi, const unsigned short* Klo,
    const unsigned short* Vthi, const unsigned short* Vtlo)
{
#pragma unroll
    for (int it = 0; it < 8; it++) {            // K hi/lo
        int idx  = tid + it * 128;
        int half = idx >> 9;
        int rem  = idx & 511;
        int r    = rem >> 3, sg = rem & 7;
        const unsigned short* src =
            (half ? Klo : Khi) + (size_t)(kb + r) * DHEAD + sg * 8;
        uint32_t dst = sbase + (uint32_t)(bufbase + half * 4608 + r * 72 + sg * 8) * 2;
        CP_ASYNC16(dst, src);
    }
#pragma unroll
    for (int it = 0; it < 8; it++) {            // Vt hi/lo
        int idx  = tid + it * 128;
        int half = idx >> 9;
        int rem  = idx & 511;
        int r    = rem >> 3, sg = rem & 7;      // r = dv row
        const unsigned short* src =
            (half ? Vtlo : Vthi) + (size_t)r * SEQ + kb + sg * 8;
        uint32_t dst = sbase + (uint32_t)(bufbase + (2 + half) * 4608 + r * 72 + sg * 8) * 2;
        CP_ASYNC16(dst, src);
    }
    CP_COMMIT();
}

__global__ __launch_bounds__(128)
void attn_mma(float* __restrict__ out)
{
    extern __shared__ char smem_raw[];
    unsigned short* sb = (unsigned short*)smem_raw;
    const uint32_t sbase = smem_u32(sb);

    const int tid  = threadIdx.x;
    const int wq   = tid >> 5;
    const int lane = tid & 31;
    const int quad = lane >> 2, pr = lane & 3;
    const int mi   = lane >> 3, l8 = lane & 7;
    const int a_rofs = l8 + (mi & 1) * 8;
    const int a_kofs = (mi >> 1) * 8;
    const int b_nofs = l8 + (mi >> 1) * 8;
    const int b_kofs = (mi & 1) * 8;

    const int qbase = blockIdx.x * 64;
    const int bh    = blockIdx.y;

    const unsigned short* Qhi = g_qhi + (size_t)bh * SEQ * DHEAD;
    const unsigned short* Qlo = g_qlo + (size_t)bh * SEQ * DHEAD;
    const unsigned short* Khi = g_khi + (size_t)bh * SEQ * DHEAD;
    const unsigned short* Klo = g_klo + (size_t)bh * SEQ * DHEAD;
    const unsigned short* Vthi = g_vthi + (size_t)bh * DHEAD * SEQ;
    const unsigned short* Vtlo = g_vtlo + (size_t)bh * DHEAD * SEQ;

    // prologue: Q tile + chunk 0
#pragma unroll
    for (int it = 0; it < 8; it++) {
        int idx  = tid + it * 128;
        int half = idx >> 9;
        int rem  = idx & 511;
        int r    = rem >> 3, sg = rem & 7;
        const unsigned short* src =
            (half ? Qlo : Qhi) + (size_t)(qbase + r) * DHEAD + sg * 8;
        uint32_t dst = sbase + (uint32_t)((half ? TQ_LO : TQ_HI) + r * 72 + sg * 8) * 2;
        CP_ASYNC16(dst, src);
    }
    attn_load_chunk(sbase, tid, 0, BUF0, Khi, Klo, Vthi, Vtlo);

    float oacc[8][4];
    float mrow[2] = {-1e30f, -1e30f}, lrow[2] = {0.f, 0.f};
#pragma unroll
    for (int nt = 0; nt < 8; nt++)
#pragma unroll
        for (int e = 0; e < 4; e++) oacc[nt][e] = 0.f;

    const int NCHUNK = SEQ / 64;
    for (int i = 0; i < NCHUNK; i++) {
        CP_WAIT0();
        __syncthreads();
        if (i + 1 < NCHUNK)
            attn_load_chunk(sbase, tid, (i + 1) * 64,
                            BUF0 + ((i + 1) & 1) * BUFSZ, Khi, Klo, Vthi, Vtlo);

        const int Bb   = BUF0 + (i & 1) * BUFSZ;
        const int TKHI = Bb,           TKLO = Bb + 4608;
        const int TVHI = Bb + 9216,    TVLO = Bb + 13824;

        // ---- QK^T ----
        float c[8][4];
#pragma unroll
        for (int nt = 0; nt < 8; nt++)
#pragma unroll
            for (int e = 0; e < 4; e++) c[nt][e] = 0.f;

#pragma unroll
        for (int ks = 0; ks < 4; ks++) {
            const int k0 = ks * 16;
            uint32_t qh[4], ql[4];
            {
                int r = wq * 16 + a_rofs;
                LDMATRIX_X4(qh[0], qh[1], qh[2], qh[3],
                            sbase + (uint32_t)(TQ_HI + r * 72 + k0 + a_kofs) * 2);
                LDMATRIX_X4(ql[0], ql[1], ql[2], ql[3],
                            sbase + (uint32_t)(TQ_LO + r * 72 + k0 + a_kofs) * 2);
            }
#pragma unroll
            for (int np = 0; np < 4; np++) {
                int n = np * 16 + b_nofs;
                uint32_t kh[4], kl[4];
                LDMATRIX_X4(kh[0], kh[1], kh[2], kh[3],
                            sbase + (uint32_t)(TKHI + n * 72 + k0 + b_kofs) * 2);
                LDMATRIX_X4(kl[0], kl[1], kl[2], kl[3],
                            sbase + (uint32_t)(TKLO + n * 72 + k0 + b_kofs) * 2);
                uint32_t b0h[2] = {kh[0], kh[1]}, b1h[2] = {kh[2], kh[3]};
                uint32_t b0l[2] = {kl[0], kl[1]}, b1l[2] = {kl[2], kl[3]};
                mma_bf16(c[np*2],   qh, b0h);
                mma_bf16(c[np*2],   qh, b0l);
                mma_bf16(c[np*2],   ql, b0h);
                mma_bf16(c[np*2+1], qh, b1h);
                mma_bf16(c[np*2+1], qh, b1l);
                mma_bf16(c[np*2+1], ql, b1h);
            }
        }

        // ---- online softmax (rows quad / quad+8; 4 lanes per row) ----
#pragma unroll
        for (int r = 0; r < 2; r++) {
            const int e = r * 2;
            float mx = c[0][e];
#pragma unroll
            for (int nt = 0; nt < 8; nt++)
                mx = fmaxf(mx, fmaxf(c[nt][e], c[nt][e+1]));
            mx = fmaxf(mx, __shfl_xor_sync(0xffffffffu, mx, 1));
            mx = fmaxf(mx, __shfl_xor_sync(0xffffffffu, mx, 2));
            float mnew  = fmaxf(mrow[r], mx);
            float alpha = __expf(mrow[r] - mnew);
            float ps = 0.f;
#pragma unroll
            for (int nt = 0; nt < 8; nt++) {
                c[nt][e]   = __expf(c[nt][e]   - mnew);
                c[nt][e+1] = __expf(c[nt][e+1] - mnew);
                ps += c[nt][e] + c[nt][e+1];
            }
            ps += __shfl_xor_sync(0xffffffffu, ps, 1);
            ps += __shfl_xor_sync(0xffffffffu, ps, 2);
            lrow[r] = lrow[r] * alpha + ps;
            mrow[r] = mnew;
#pragma unroll
            for (int nt = 0; nt < 8; nt++) {
                oacc[nt][e]   *= alpha;
                oacc[nt][e+1] *= alpha;
            }
        }

        // ---- PV: P fragments straight from C fragments ----
#pragma unroll
        for (int ks = 0; ks < 4; ks++) {
            uint32_t ph[4], pl[4];
            split_pack2(c[2*ks][0],   c[2*ks][1],   ph[0], pl[0]);
            split_pack2(c[2*ks][2],   c[2*ks][3],   ph[1], pl[1]);
            split_pack2(c[2*ks+1][0], c[2*ks+1][1], ph[2], pl[2]);
            split_pack2(c[2*ks+1][2], c[2*ks+1][3], ph[3], pl[3]);
#pragma unroll
            for (int np = 0; np < 4; np++) {
                int n = np * 16 + b_nofs;
                uint32_t vh[4], vl[4];
                LDMATRIX_X4(vh[0], vh[1], vh[2], vh[3],
                            sbase + (uint32_t)(TVHI + n * 72 + ks * 16 + b_kofs) * 2);
                LDMATRIX_X4(vl[0], vl[1], vl[2], vl[3],
                            sbase + (uint32_t)(TVLO + n * 72 + ks * 16 + b_kofs) * 2);
                uint32_t b0h[2] = {vh[0], vh[1]}, b1h[2] = {vh[2], vh[3]};
                uint32_t b0l[2] = {vl[0], vl[1]}, b1l[2] = {vl[2], vl[3]};
                mma_bf16(oacc[np*2],   ph, b0h);
                mma_bf16(oacc[np*2],   ph, b0l);
                mma_bf16(oacc[np*2],   pl, b0h);
                mma_bf16(oacc[np*2+1], ph, b1h);
                mma_bf16(oacc[np*2+1], ph, b1l);
                mma_bf16(oacc[np*2+1], pl, b1h);
            }
        }
    }

    // ---- epilogue: out[b][s][h*64+dv] = oacc / (l * 8) ----
    const int b = bh >> 4, h = bh & 15;
#pragma unroll
    for (int half = 0; half < 2; half++) {
        int srow = qbase + wq * 16 + quad + half * 8;
        float inv = 1.0f / (lrow[half] * 8.0f);
        float* dst = out + ((size_t)(b * SEQ + srow)) * (NHEADS * DHEAD) + h * DHEAD;
#pragma unroll
        for (int nt = 0; nt < 8; nt++) {
            int col = nt * 8 + pr * 2;
            float2 v;
            v.x = oacc[nt][half*2 + 0] * inv;
            v.y = oacc[nt][half*2 + 1] * inv;
            *(float2*)(dst + col) = v;
        }
    }
}

// ---------------------------------------------------------------------------
extern "C" void kernel_launch(void* const* d_in, const int* in_sizes, int n_in,
                              void* d_out, int out_size)
{
    const float* x  = (const float*)d_in[0];
    const float* Wq = (const float*)d_in[1];
    const float* bq = (const float*)d_in[2];
    const float* Wk = (const float*)d_in[3];
    const float* bk = (const float*)d_in[4];
    const float* Wv = (const float*)d_in[5];
    const float* bv = (const float*)d_in[6];
    float* out = (float*)d_out;

    cudaFuncSetAttribute(proj_mma, cudaFuncAttributeMaxDynamicSharedMemorySize,
                         PROJ_SMEM_ELEMS * 2);
    cudaFuncSetAttribute(attn_mma, cudaFuncAttributeMaxDynamicSharedMemorySize,
                         ATTN_SMEM_BYTES);

    convert_x<<<(NTOK * INDIM / 4) / 256, 256>>>(x);
    convert_w<<<dim3(INDIM / 64, NHEADS * 3), 256>>>(Wq, Wk, Wv);
    proj_mma<<<dim3(NTOK / 128, NHEADS, 3), 128, PROJ_SMEM_ELEMS * 2>>>(bq, bk, bv);
    convert_vt<<<dim3(SEQ / 64, BH), 256>>>();
    attn_mma<<<dim3(SEQ / 64, BH), 128, ATTN_SMEM_BYTES>>>(out);
}

// round 12
// speedup vs baseline: 3.2051x; 1.1209x over previous
#include <cuda_runtime.h>
#include <cuda_bf16.h>
#include <stdint.h>
#include <math.h>

#define NHEADS 16
#define INDIM  1024
#define DHEAD  64
#define BATCH  2
#define SEQ    2048
#define NTOK   (BATCH*SEQ)
#define BH     (BATCH*NHEADS)

// fp32 V scratch (needed for the transpose pass), layout [B*H][S][DHEAD]
__device__ float g_v[(size_t)BH*SEQ*DHEAD];

// Split-precision inputs for bf16 tensor-core MMA (raw u16 payloads).
__device__ unsigned short g_xhi[(size_t)NTOK*INDIM];
__device__ unsigned short g_xlo[(size_t)NTOK*INDIM];
__device__ unsigned short g_wthi[(size_t)NHEADS*3*DHEAD*INDIM];
__device__ unsigned short g_wtlo[(size_t)NHEADS*3*DHEAD*INDIM];

// Split q/k bf16 ([bh][s][d]); transposed v as FP16 hi/lo ([bh][d][s]).
__device__ unsigned short g_qhi[(size_t)BH*SEQ*DHEAD];
__device__ unsigned short g_qlo[(size_t)BH*SEQ*DHEAD];
__device__ unsigned short g_khi[(size_t)BH*SEQ*DHEAD];
__device__ unsigned short g_klo[(size_t)BH*SEQ*DHEAD];
__device__ unsigned short g_vthi[(size_t)BH*DHEAD*SEQ];   // fp16
__device__ unsigned short g_vtlo[(size_t)BH*DHEAD*SEQ];   // fp16 residual

__device__ __forceinline__ uint32_t smem_u32(const void* p) {
    uint32_t a;
    asm("{ .reg .u64 t; cvta.to.shared.u64 t, %1; cvt.u32.u64 %0, t; }"
        : "=r"(a) : "l"(p));
    return a;
}

__device__ __forceinline__ unsigned short f2bf_hi(float f) {
    __nv_bfloat16 h = __float2bfloat16(f);
    __nv_bfloat16_raw r = *(__nv_bfloat16_raw*)&h;
    return r.x;
}
__device__ __forceinline__ float bf2f(unsigned short u) {
    return __uint_as_float((uint32_t)u << 16);
}
// fp16 conversions via bare PTX (no cuda_fp16.h dependency)
__device__ __forceinline__ unsigned short f2h_raw(float f) {
    unsigned short r;
    asm("cvt.rn.f16.f32 %0, %1;" : "=h"(r) : "f"(f));
    return r;
}
__device__ __forceinline__ float h2f(unsigned short u) {
    float f;
    asm("cvt.f32.f16 %0, %1;" : "=f"(f) : "h"(u));
    return f;
}
// pack two floats to fp16x2 (lo = x, hi = y) in one cvt
__device__ __forceinline__ uint32_t pack_h2(float x, float y) {
    uint32_t r;
    asm("cvt.rn.f16x2.f32 %0, %1, %2;" : "=r"(r) : "f"(y), "f"(x));
    return r;
}

// split (x,y) -> bf16 hi-pair and bf16 residual-pair (lower 16 bits = x)
__device__ __forceinline__ void split_pack2(float x, float y,
                                            uint32_t& hi, uint32_t& lo) {
    unsigned short hx = f2bf_hi(x), hy = f2bf_hi(y);
    float rx = x - bf2f(hx);
    float ry = y - bf2f(hy);
    hi = (uint32_t)hx | ((uint32_t)hy << 16);
    lo = (uint32_t)f2bf_hi(rx) | ((uint32_t)f2bf_hi(ry) << 16);
}

// bf16 mma: D(f32) = A(bf16,row) x B(bf16,col) + C, m16n8k16.
__device__ __forceinline__ void mma_bf16(float* c, const uint32_t* a,
                                         const uint32_t* b) {
    float d0, d1, d2, d3;
    asm volatile(
        "mma.sync.aligned.m16n8k16.row.col.f32.bf16.bf16.f32 "
        "{%0,%1,%2,%3}, {%4,%5,%6,%7}, {%8,%9}, {%10,%11,%12,%13};"
        : "=f"(d0), "=f"(d1), "=f"(d2), "=f"(d3)
        : "r"(a[0]), "r"(a[1]), "r"(a[2]), "r"(a[3]),
          "r"(b[0]), "r"(b[1]),
          "f"(c[0]), "f"(c[1]), "f"(c[2]), "f"(c[3]));
    c[0] = d0; c[1] = d1; c[2] = d2; c[3] = d3;
}

// fp16 mma: D(f32) = A(f16,row) x B(f16,col) + C, m16n8k16.
__device__ __forceinline__ void mma_f16(float* c, const uint32_t* a,
                                        const uint32_t* b) {
    float d0, d1, d2, d3;
    asm volatile(
        "mma.sync.aligned.m16n8k16.row.col.f32.f16.f16.f32 "
        "{%0,%1,%2,%3}, {%4,%5,%6,%7}, {%8,%9}, {%10,%11,%12,%13};"
        : "=f"(d0), "=f"(d1), "=f"(d2), "=f"(d3)
        : "r"(a[0]), "r"(a[1]), "r"(a[2]), "r"(a[3]),
          "r"(b[0]), "r"(b[1]),
          "f"(c[0]), "f"(c[1]), "f"(c[2]), "f"(c[3]));
    c[0] = d0; c[1] = d1; c[2] = d2; c[3] = d3;
}

#define LDMATRIX_X4(r0, r1, r2, r3, addr)                                      \
    asm volatile("ldmatrix.sync.aligned.m8n8.x4.shared.b16 {%0,%1,%2,%3}, [%4];" \
                 : "=r"(r0), "=r"(r1), "=r"(r2), "=r"(r3) : "r"(addr))

#define CP_ASYNC16(smem_addr, gptr)                                            \
    asm volatile("cp.async.cg.shared.global [%0], [%1], 16;"                   \
                 :: "r"(smem_addr), "l"(gptr) : "memory")
#define CP_COMMIT()  asm volatile("cp.async.commit_group;" ::: "memory")
#define CP_WAIT0()   asm volatile("cp.async.wait_group 0;" ::: "memory")

// ---------------------------------------------------------------------------
__global__ __launch_bounds__(256)
void convert_x(const float* __restrict__ x)
{
    int i = blockIdx.x * 256 + threadIdx.x;
    float4 v = ((const float4*)x)[i];
    float f[4] = {v.x, v.y, v.z, v.w};
    ushort4 hh, ll;
    unsigned short* hp = (unsigned short*)&hh;
    unsigned short* lp = (unsigned short*)&ll;
#pragma unroll
    for (int j = 0; j < 4; j++) {
        unsigned short hu = f2bf_hi(f[j]);
        hp[j] = hu; lp[j] = f2bf_hi(f[j] - bf2f(hu));
    }
    ((ushort4*)g_xhi)[i] = hh;
    ((ushort4*)g_xlo)[i] = ll;
}

// ---------------------------------------------------------------------------
__global__ __launch_bounds__(256)
void convert_w(const float* __restrict__ Wq, const float* __restrict__ Wk,
               const float* __restrict__ Wv)
{
    __shared__ float tile[64][65];
    const int k0 = blockIdx.x * 64;
    const int hp = blockIdx.y;
    const int h  = hp / 3, p = hp % 3;
    const float* W = ((p == 0) ? Wq : (p == 1) ? Wk : Wv) + (size_t)h * INDIM * DHEAD;
    const int tid = threadIdx.x;

#pragma unroll
    for (int it = 0; it < 16; it++) {
        int idx = tid + it * 256;
        int kk = idx >> 6, n = idx & 63;
        tile[kk][n] = W[(size_t)(k0 + kk) * DHEAD + n];
    }
    __syncthreads();
#pragma unroll
    for (int it = 0; it < 16; it++) {
        int idx = tid + it * 256;
        int n = idx >> 6, kk = idx & 63;
        float v = tile[kk][n];
        unsigned short hu = f2bf_hi(v);
        size_t o = (size_t)hp * DHEAD * INDIM + (size_t)n * INDIM + k0 + kk;
        g_wthi[o] = hu; g_wtlo[o] = f2bf_hi(v - bf2f(hu));
    }
}

// ---------------------------------------------------------------------------
// proj_mma: validated; epilogue writes q/k as split bf16 hi/lo, v as fp32.
// ---------------------------------------------------------------------------
#define AHI_OFF 0
#define ALO_OFF (128*72)
#define BHI_OFF (2*128*72)
#define BLO_OFF (2*128*72 + 64*72)
#define PROJ_SMEM_ELEMS (2*128*72 + 2*64*72)

__global__ __launch_bounds__(128)
void proj_mma(const float* __restrict__ bq, const float* __restrict__ bk,
              const float* __restrict__ bv)
{
    extern __shared__ char smem_raw[];
    unsigned short* sb = (unsigned short*)smem_raw;
    const uint32_t sbase = smem_u32(sb);

    const int tid  = threadIdx.x;
    const int wid  = tid >> 5;
    const int lane = tid & 31;
    const int mbase = blockIdx.x * 128;
    const int h     = blockIdx.y;
    const int p     = blockIdx.z;

    const unsigned short* Whi = g_wthi + (size_t)(h * 3 + p) * DHEAD * INDIM;
    const unsigned short* Wlo = g_wtlo + (size_t)(h * 3 + p) * DHEAD * INDIM;

    float acc[2][8][4];
#pragma unroll
    for (int mt = 0; mt < 2; mt++)
#pragma unroll
        for (int nt = 0; nt < 8; nt++)
#pragma unroll
            for (int e = 0; e < 4; e++) acc[mt][nt][e] = 0.f;

    const int mi   = lane >> 3;
    const int l8   = lane & 7;
    const int a_rofs = l8 + (mi & 1) * 8;
    const int a_kofs = (mi >> 1) * 8;
    const int b_nofs = l8 + (mi >> 1) * 8;
    const int b_kofs = (mi & 1) * 8;

    for (int c = 0; c < 16; c++) {
        __syncthreads();
#pragma unroll
        for (int it = 0; it < 8; it++) {
            int idx = tid + it * 128;
            int r = idx >> 3, sg = idx & 7;
            *(uint4*)(sb + AHI_OFF + r * 72 + sg * 8) =
                *(const uint4*)(g_xhi + (size_t)(mbase + r) * INDIM + c * 64 + sg * 8);
            *(uint4*)(sb + ALO_OFF + r * 72 + sg * 8) =
                *(const uint4*)(g_xlo + (size_t)(mbase + r) * INDIM + c * 64 + sg * 8);
        }
#pragma unroll
        for (int it = 0; it < 4; it++) {
            int idx = tid + it * 128;
            int n = idx >> 3, sg = idx & 7;
            *(uint4*)(sb + BHI_OFF + n * 72 + sg * 8) =
                *(const uint4*)(Whi + (size_t)n * INDIM + c * 64 + sg * 8);
            *(uint4*)(sb + BLO_OFF + n * 72 + sg * 8) =
                *(const uint4*)(Wlo + (size_t)n * INDIM + c * 64 + sg * 8);
        }
        __syncthreads();

#pragma unroll
        for (int ks = 0; ks < 4; ks++) {
            const int k0 = ks * 16;
            uint32_t bhi[8][2], blo[8][2];
#pragma unroll
            for (int np = 0; np < 4; np++) {
                int n = np * 16 + b_nofs;
                uint32_t ah = sbase + (uint32_t)(BHI_OFF + n * 72 + k0 + b_kofs) * 2;
                uint32_t al = sbase + (uint32_t)(BLO_OFF + n * 72 + k0 + b_kofs) * 2;
                LDMATRIX_X4(bhi[np*2][0], bhi[np*2][1], bhi[np*2+1][0], bhi[np*2+1][1], ah);
                LDMATRIX_X4(blo[np*2][0], blo[np*2][1], blo[np*2+1][0], blo[np*2+1][1], al);
            }
#pragma unroll
            for (int mt = 0; mt < 2; mt++) {
                int r = wid * 32 + mt * 16 + a_rofs;
                uint32_t ahad = sbase + (uint32_t)(AHI_OFF + r * 72 + k0 + a_kofs) * 2;
                uint32_t alad = sbase + (uint32_t)(ALO_OFF + r * 72 + k0 + a_kofs) * 2;
                uint32_t ah[4], al[4];
                LDMATRIX_X4(ah[0], ah[1], ah[2], ah[3], ahad);
                LDMATRIX_X4(al[0], al[1], al[2], al[3], alad);
#pragma unroll
                for (int nt = 0; nt < 8; nt++) {
                    mma_bf16(acc[mt][nt], ah, bhi[nt]);
                    mma_bf16(acc[mt][nt], ah, blo[nt]);
                    mma_bf16(acc[mt][nt], al, bhi[nt]);
                }
            }
        }
    }

    const float* bias = ((p == 0) ? bq : (p == 1) ? bk : bv) + h * DHEAD;
    const int quad = lane >> 2, pr = lane & 3;

#pragma unroll
    for (int mt = 0; mt < 2; mt++) {
#pragma unroll
        for (int half = 0; half < 2; half++) {
            int tok = mbase + wid * 32 + mt * 16 + quad + half * 8;
            int b = tok >> 11, s = tok & 2047;
            size_t base = ((size_t)(b * NHEADS + h) * SEQ + s) * DHEAD;
            if (p < 2) {
                unsigned short* dhi = p ? g_khi : g_qhi;
                unsigned short* dlo = p ? g_klo : g_qlo;
#pragma unroll
                for (int nt = 0; nt < 8; nt++) {
                    int col = nt * 8 + pr * 2;
                    float2 bb = *(const float2*)(bias + col);
                    uint32_t ph, pl;
                    split_pack2(acc[mt][nt][half*2 + 0] + bb.x,
                                acc[mt][nt][half*2 + 1] + bb.y, ph, pl);
                    *(uint32_t*)(dhi + base + col) = ph;
                    *(uint32_t*)(dlo + base + col) = pl;
                }
            } else {
                float* dst = g_v + base;
#pragma unroll
                for (int nt = 0; nt < 8; nt++) {
                    int col = nt * 8 + pr * 2;
                    float2 bb = *(const float2*)(bias + col);
                    float2 v;
                    v.x = acc[mt][nt][half*2 + 0] + bb.x;
                    v.y = acc[mt][nt][half*2 + 1] + bb.y;
                    *(float2*)(dst + col) = v;
                }
            }
        }
    }
}

// ---------------------------------------------------------------------------
// convert_vt: v fp32 [bh][s][d] -> FP16 hi + fp16 residual, [bh][d][s].
// ---------------------------------------------------------------------------
__global__ __launch_bounds__(256)
void convert_vt()
{
    __shared__ float tile[64][65];
    const int s0 = blockIdx.x * 64;
    const int bh = blockIdx.y;
    const int tid = threadIdx.x;
    const float* V = g_v + (size_t)bh * SEQ * DHEAD;

#pragma unroll
    for (int it = 0; it < 16; it++) {
        int idx = tid + it * 256;
        int r = idx >> 6, d = idx & 63;
        tile[r][d] = V[(size_t)(s0 + r) * DHEAD + d];
    }
    __syncthreads();
#pragma unroll
    for (int it = 0; it < 16; it++) {
        int idx = tid + it * 256;
        int d = idx >> 6, cc = idx & 63;
        float v = tile[cc][d];
        unsigned short hu = f2h_raw(v);
        size_t o = (size_t)bh * DHEAD * SEQ + (size_t)d * SEQ + s0 + cc;
        g_vthi[o] = hu; g_vtlo[o] = f2h_raw(v - h2f(hu));
    }
}

// ---------------------------------------------------------------------------
// attn_mma: QK^T = bf16 3-term; PV = fp16, single-P x split-V (2 MMAs).
// cp.async 2-stage ring (validated round 10).
// ---------------------------------------------------------------------------
#define TQ_HI 0
#define TQ_LO 4608            // 64*72
#define BUF0  9216            // 2*64*72
#define BUFSZ 18432           // 4*64*72
#define ATTN_SMEM_BYTES ((2*4608 + 2*BUFSZ) * 2)   // 92160 B

__device__ __forceinline__ void attn_load_chunk(
    uint32_t sbase, int tid, int kb, int bufbase,
    const unsigned short* Khi, const unsigned short* Klo,
    const unsigned short* Vthi, const unsigned short* Vtlo)
{
#pragma unroll
    for (int it = 0; it < 8; it++) {            // K hi/lo (bf16)
        int idx  = tid + it * 128;
        int half = idx >> 9;
        int rem  = idx & 511;
        int r    = rem >> 3, sg = rem & 7;
        const unsigned short* src =
            (half ? Klo : Khi) + (size_t)(kb + r) * DHEAD + sg * 8;
        uint32_t dst = sbase + (uint32_t)(bufbase + half * 4608 + r * 72 + sg * 8) * 2;
        CP_ASYNC16(dst, src);
    }
#pragma unroll
    for (int it = 0; it < 8; it++) {            // Vt hi/lo (fp16)
        int idx  = tid + it * 128;
        int half = idx >> 9;
        int rem  = idx & 511;
        int r    = rem >> 3, sg = rem & 7;      // r = dv row
        const unsigned short* src =
            (half ? Vtlo : Vthi) + (size_t)r * SEQ + kb + sg * 8;
        uint32_t dst = sbase + (uint32_t)(bufbase + (2 + half) * 4608 + r * 72 + sg * 8) * 2;
        CP_ASYNC16(dst, src);
    }
    CP_COMMIT();
}

__global__ __launch_bounds__(128)
void attn_mma(float* __restrict__ out)
{
    extern __shared__ char smem_raw[];
    unsigned short* sb = (unsigned short*)smem_raw;
    const uint32_t sbase = smem_u32(sb);

    const int tid  = threadIdx.x;
    const int wq   = tid >> 5;
    const int lane = tid & 31;
    const int quad = lane >> 2, pr = lane & 3;
    const int mi   = lane >> 3, l8 = lane & 7;
    const int a_rofs = l8 + (mi & 1) * 8;
    const int a_kofs = (mi >> 1) * 8;
    const int b_nofs = l8 + (mi >> 1) * 8;
    const int b_kofs = (mi & 1) * 8;

    const int qbase = blockIdx.x * 64;
    const int bh    = blockIdx.y;

    const unsigned short* Qhi = g_qhi + (size_t)bh * SEQ * DHEAD;
    const unsigned short* Qlo = g_qlo + (size_t)bh * SEQ * DHEAD;
    const unsigned short* Khi = g_khi + (size_t)bh * SEQ * DHEAD;
    const unsigned short* Klo = g_klo + (size_t)bh * SEQ * DHEAD;
    const unsigned short* Vthi = g_vthi + (size_t)bh * DHEAD * SEQ;
    const unsigned short* Vtlo = g_vtlo + (size_t)bh * DHEAD * SEQ;

    // prologue: Q tile + chunk 0
#pragma unroll
    for (int it = 0; it < 8; it++) {
        int idx  = tid + it * 128;
        int half = idx >> 9;
        int rem  = idx & 511;
        int r    = rem >> 3, sg = rem & 7;
        const unsigned short* src =
            (half ? Qlo : Qhi) + (size_t)(qbase + r) * DHEAD + sg * 8;
        uint32_t dst = sbase + (uint32_t)((half ? TQ_LO : TQ_HI) + r * 72 + sg * 8) * 2;
        CP_ASYNC16(dst, src);
    }
    attn_load_chunk(sbase, tid, 0, BUF0, Khi, Klo, Vthi, Vtlo);

    float oacc[8][4];
    float mrow[2] = {-1e30f, -1e30f}, lrow[2] = {0.f, 0.f};
#pragma unroll
    for (int nt = 0; nt < 8; nt++)
#pragma unroll
        for (int e = 0; e < 4; e++) oacc[nt][e] = 0.f;

    const int NCHUNK = SEQ / 64;
    for (int i = 0; i < NCHUNK; i++) {
        CP_WAIT0();
        __syncthreads();
        if (i + 1 < NCHUNK)
            attn_load_chunk(sbase, tid, (i + 1) * 64,
                            BUF0 + ((i + 1) & 1) * BUFSZ, Khi, Klo, Vthi, Vtlo);

        const int Bb   = BUF0 + (i & 1) * BUFSZ;
        const int TKHI = Bb,           TKLO = Bb + 4608;
        const int TVHI = Bb + 9216,    TVLO = Bb + 13824;

        // ---- QK^T (bf16, 3-term) ----
        float c[8][4];
#pragma unroll
        for (int nt = 0; nt < 8; nt++)
#pragma unroll
            for (int e = 0; e < 4; e++) c[nt][e] = 0.f;

#pragma unroll
        for (int ks = 0; ks < 4; ks++) {
            const int k0 = ks * 16;
            uint32_t qh[4], ql[4];
            {
                int r = wq * 16 + a_rofs;
                LDMATRIX_X4(qh[0], qh[1], qh[2], qh[3],
                            sbase + (uint32_t)(TQ_HI + r * 72 + k0 + a_kofs) * 2);
                LDMATRIX_X4(ql[0], ql[1], ql[2], ql[3],
                            sbase + (uint32_t)(TQ_LO + r * 72 + k0 + a_kofs) * 2);
            }
#pragma unroll
            for (int np = 0; np < 4; np++) {
                int n = np * 16 + b_nofs;
                uint32_t kh[4], kl[4];
                LDMATRIX_X4(kh[0], kh[1], kh[2], kh[3],
                            sbase + (uint32_t)(TKHI + n * 72 + k0 + b_kofs) * 2);
                LDMATRIX_X4(kl[0], kl[1], kl[2], kl[3],
                            sbase + (uint32_t)(TKLO + n * 72 + k0 + b_kofs) * 2);
                uint32_t b0h[2] = {kh[0], kh[1]}, b1h[2] = {kh[2], kh[3]};
                uint32_t b0l[2] = {kl[0], kl[1]}, b1l[2] = {kl[2], kl[3]};
                mma_bf16(c[np*2],   qh, b0h);
                mma_bf16(c[np*2],   qh, b0l);
                mma_bf16(c[np*2],   ql, b0h);
                mma_bf16(c[np*2+1], qh, b1h);
                mma_bf16(c[np*2+1], qh, b1l);
                mma_bf16(c[np*2+1], ql, b1h);
            }
        }

        // ---- online softmax (rows quad / quad+8; 4 lanes per row) ----
#pragma unroll
        for (int r = 0; r < 2; r++) {
            const int e = r * 2;
            float mx = c[0][e];
#pragma unroll
            for (int nt = 0; nt < 8; nt++)
                mx = fmaxf(mx, fmaxf(c[nt][e], c[nt][e+1]));
            mx = fmaxf(mx, __shfl_xor_sync(0xffffffffu, mx, 1));
            mx = fmaxf(mx, __shfl_xor_sync(0xffffffffu, mx, 2));
            float mnew  = fmaxf(mrow[r], mx);
            float alpha = __expf(mrow[r] - mnew);
            float ps = 0.f;
#pragma unroll
            for (int nt = 0; nt < 8; nt++) {
                c[nt][e]   = __expf(c[nt][e]   - mnew);
                c[nt][e+1] = __expf(c[nt][e+1] - mnew);
                ps += c[nt][e] + c[nt][e+1];
            }
            ps += __shfl_xor_sync(0xffffffffu, ps, 1);
            ps += __shfl_xor_sync(0xffffffffu, ps, 2);
            lrow[r] = lrow[r] * alpha + ps;
            mrow[r] = mnew;
#pragma unroll
            for (int nt = 0; nt < 8; nt++) {
                oacc[nt][e]   *= alpha;
                oacc[nt][e+1] *= alpha;
            }
        }

        // ---- PV (fp16): single-P fragments x split-V, 2 MMAs per n-tile ----
#pragma unroll
        for (int ks = 0; ks < 4; ks++) {
            uint32_t ph[4];
            ph[0] = pack_h2(c[2*ks][0],   c[2*ks][1]);
            ph[1] = pack_h2(c[2*ks][2],   c[2*ks][3]);
            ph[2] = pack_h2(c[2*ks+1][0], c[2*ks+1][1]);
            ph[3] = pack_h2(c[2*ks+1][2], c[2*ks+1][3]);
#pragma unroll
            for (int np = 0; np < 4; np++) {
                int n = np * 16 + b_nofs;
                uint32_t vh[4], vl[4];
                LDMATRIX_X4(vh[0], vh[1], vh[2], vh[3],
                            sbase + (uint32_t)(TVHI + n * 72 + ks * 16 + b_kofs) * 2);
                LDMATRIX_X4(vl[0], vl[1], vl[2], vl[3],
                            sbase + (uint32_t)(TVLO + n * 72 + ks * 16 + b_kofs) * 2);
                uint32_t b0h[2] = {vh[0], vh[1]}, b1h[2] = {vh[2], vh[3]};
                uint32_t b0l[2] = {vl[0], vl[1]}, b1l[2] = {vl[2], vl[3]};
                mma_f16(oacc[np*2],   ph, b0h);
                mma_f16(oacc[np*2],   ph, b0l);
                mma_f16(oacc[np*2+1], ph, b1h);
                mma_f16(oacc[np*2+1], ph, b1l);
            }
        }
    }

    // ---- epilogue: out[b][s][h*64+dv] = oacc / (l * 8) ----
    const int b = bh >> 4, h = bh & 15;
#pragma unroll
    for (int half = 0; half < 2; half++) {
        int srow = qbase + wq * 16 + quad + half * 8;
        float inv = 1.0f / (lrow[half] * 8.0f);
        float* dst = out + ((size_t)(b * SEQ + srow)) * (NHEADS * DHEAD) + h * DHEAD;
#pragma unroll
        for (int nt = 0; nt < 8; nt++) {
            int col = nt * 8 + pr * 2;
            float2 v;
            v.x = oacc[nt][half*2 + 0] * inv;
            v.y = oacc[nt][half*2 + 1] * inv;
            *(float2*)(dst + col) = v;
        }
    }
}

// ---------------------------------------------------------------------------
extern "C" void kernel_launch(void* const* d_in, const int* in_sizes, int n_in,
                              void* d_out, int out_size)
{
    const float* x  = (const float*)d_in[0];
    const float* Wq = (const float*)d_in[1];
    const float* bq = (const float*)d_in[2];
    const float* Wk = (const float*)d_in[3];
    const float* bk = (const float*)d_in[4];
    const float* Wv = (const float*)d_in[5];
    const float* bv = (const float*)d_in[6];
    float* out = (float*)d_out;

    cudaFuncSetAttribute(proj_mma, cudaFuncAttributeMaxDynamicSharedMemorySize,
                         PROJ_SMEM_ELEMS * 2);
    cudaFuncSetAttribute(attn_mma, cudaFuncAttributeMaxDynamicSharedMemorySize,
                         ATTN_SMEM_BYTES);

    convert_x<<<(NTOK * INDIM / 4) / 256, 256>>>(x);
    convert_w<<<dim3(INDIM / 64, NHEADS * 3), 256>>>(Wq, Wk, Wv);
    proj_mma<<<dim3(NTOK / 128, NHEADS, 3), 128, PROJ_SMEM_ELEMS * 2>>>(bq, bk, bv);
    convert_vt<<<dim3(SEQ / 64, BH), 256>>>();
    attn_mma<<<dim3(SEQ / 64, BH), 128, ATTN_SMEM_BYTES>>>(out);
}

// round 14
// speedup vs baseline: 3.8742x; 1.2088x over previous
#include <cuda_runtime.h>
#include <cuda_bf16.h>
#include <stdint.h>
#include <math.h>

#define NHEADS 16
#define INDIM  1024
#define DHEAD  64
#define BATCH  2
#define SEQ    2048
#define NTOK   (BATCH*SEQ)
#define BH     (BATCH*NHEADS)

// fp32 V scratch (needed for the transpose pass), layout [B*H][S][DHEAD]
__device__ float g_v[(size_t)BH*SEQ*DHEAD];

// Split-precision inputs for bf16 tensor-core MMA (raw u16 payloads).
__device__ unsigned short g_xhi[(size_t)NTOK*INDIM];
__device__ unsigned short g_xlo[(size_t)NTOK*INDIM];
__device__ unsigned short g_wthi[(size_t)NHEADS*3*DHEAD*INDIM];
__device__ unsigned short g_wtlo[(size_t)NHEADS*3*DHEAD*INDIM];

// Attention operands: q fp16 hi/lo split, k single fp16 ([bh][s][d]);
// v transposed fp16 hi/lo ([bh][d][s]).
__device__ unsigned short g_qhi[(size_t)BH*SEQ*DHEAD];
__device__ unsigned short g_qlo[(size_t)BH*SEQ*DHEAD];
__device__ unsigned short g_khi[(size_t)BH*SEQ*DHEAD];
__device__ unsigned short g_vthi[(size_t)BH*DHEAD*SEQ];
__device__ unsigned short g_vtlo[(size_t)BH*DHEAD*SEQ];

__device__ __forceinline__ uint32_t smem_u32(const void* p) {
    uint32_t a;
    asm("{ .reg .u64 t; cvta.to.shared.u64 t, %1; cvt.u32.u64 %0, t; }"
        : "=r"(a) : "l"(p));
    return a;
}

__device__ __forceinline__ unsigned short f2bf_hi(float f) {
    __nv_bfloat16 h = __float2bfloat16(f);
    __nv_bfloat16_raw r = *(__nv_bfloat16_raw*)&h;
    return r.x;
}
__device__ __forceinline__ float bf2f(unsigned short u) {
    return __uint_as_float((uint32_t)u << 16);
}
// fp16 conversions via bare PTX (no cuda_fp16.h dependency)
__device__ __forceinline__ unsigned short f2h_raw(float f) {
    unsigned short r;
    asm("cvt.rn.f16.f32 %0, %1;" : "=h"(r) : "f"(f));
    return r;
}
__device__ __forceinline__ float h2f(unsigned short u) {
    float f;
    asm("cvt.f32.f16 %0, %1;" : "=f"(f) : "h"(u));
    return f;
}
// pack two floats to fp16x2 (lo = x, hi = y) in one cvt
__device__ __forceinline__ uint32_t pack_h2(float x, float y) {
    uint32_t r;
    asm("cvt.rn.f16x2.f32 %0, %1, %2;" : "=r"(r) : "f"(y), "f"(x));
    return r;
}

// split (x,y) -> fp16 hi-pair and fp16 residual-pair (lower 16 bits = x)
__device__ __forceinline__ void split_pack2_h(float x, float y,
                                              uint32_t& hi, uint32_t& lo) {
    unsigned short hx = f2h_raw(x), hy = f2h_raw(y);
    float rx = x - h2f(hx);
    float ry = y - h2f(hy);
    hi = (uint32_t)hx | ((uint32_t)hy << 16);
    lo = (uint32_t)f2h_raw(rx) | ((uint32_t)f2h_raw(ry) << 16);
}

// bf16 mma: D(f32) = A(bf16,row) x B(bf16,col) + C, m16n8k16.
__device__ __forceinline__ void mma_bf16(float* c, const uint32_t* a,
                                         const uint32_t* b) {
    float d0, d1, d2, d3;
    asm volatile(
        "mma.sync.aligned.m16n8k16.row.col.f32.bf16.bf16.f32 "
        "{%0,%1,%2,%3}, {%4,%5,%6,%7}, {%8,%9}, {%10,%11,%12,%13};"
        : "=f"(d0), "=f"(d1), "=f"(d2), "=f"(d3)
        : "r"(a[0]), "r"(a[1]), "r"(a[2]), "r"(a[3]),
          "r"(b[0]), "r"(b[1]),
          "f"(c[0]), "f"(c[1]), "f"(c[2]), "f"(c[3]));
    c[0] = d0; c[1] = d1; c[2] = d2; c[3] = d3;
}

// fp16 mma: D(f32) = A(f16,row) x B(f16,col) + C, m16n8k16.
__device__ __forceinline__ void mma_f16(float* c, const uint32_t* a,
                                        const uint32_t* b) {
    float d0, d1, d2, d3;
    asm volatile(
        "mma.sync.aligned.m16n8k16.row.col.f32.f16.f16.f32 "
        "{%0,%1,%2,%3}, {%4,%5,%6,%7}, {%8,%9}, {%10,%11,%12,%13};"
        : "=f"(d0), "=f"(d1), "=f"(d2), "=f"(d3)
        : "r"(a[0]), "r"(a[1]), "r"(a[2]), "r"(a[3]),
          "r"(b[0]), "r"(b[1]),
          "f"(c[0]), "f"(c[1]), "f"(c[2]), "f"(c[3]));
    c[0] = d0; c[1] = d1; c[2] = d2; c[3] = d3;
}

#define LDMATRIX_X4(r0, r1, r2, r3, addr)                                      \
    asm volatile("ldmatrix.sync.aligned.m8n8.x4.shared.b16 {%0,%1,%2,%3}, [%4];" \
                 : "=r"(r0), "=r"(r1), "=r"(r2), "=r"(r3) : "r"(addr))

#define CP_ASYNC16(smem_addr, gptr)                                            \
    asm volatile("cp.async.cg.shared.global [%0], [%1], 16;"                   \
                 :: "r"(smem_addr), "l"(gptr) : "memory")
#define CP_COMMIT()  asm volatile("cp.async.commit_group;" ::: "memory")
#define CP_WAIT0()   asm volatile("cp.async.wait_group 0;" ::: "memory")

// ---------------------------------------------------------------------------
__global__ __launch_bounds__(256)
void convert_x(const float* __restrict__ x)
{
    int i = blockIdx.x * 256 + threadIdx.x;
    float4 v = ((const float4*)x)[i];
    float f[4] = {v.x, v.y, v.z, v.w};
    ushort4 hh, ll;
    unsigned short* hp = (unsigned short*)&hh;
    unsigned short* lp = (unsigned short*)&ll;
#pragma unroll
    for (int j = 0; j < 4; j++) {
        unsigned short hu = f2bf_hi(f[j]);
        hp[j] = hu; lp[j] = f2bf_hi(f[j] - bf2f(hu));
    }
    ((ushort4*)g_xhi)[i] = hh;
    ((ushort4*)g_xlo)[i] = ll;
}

// ---------------------------------------------------------------------------
__global__ __launch_bounds__(256)
void convert_w(const float* __restrict__ Wq, const float* __restrict__ Wk,
               const float* __restrict__ Wv)
{
    __shared__ float tile[64][65];
    const int k0 = blockIdx.x * 64;
    const int hp = blockIdx.y;
    const int h  = hp / 3, p = hp % 3;
    const float* W = ((p == 0) ? Wq : (p == 1) ? Wk : Wv) + (size_t)h * INDIM * DHEAD;
    const int tid = threadIdx.x;

#pragma unroll
    for (int it = 0; it < 16; it++) {
        int idx = tid + it * 256;
        int kk = idx >> 6, n = idx & 63;
        tile[kk][n] = W[(size_t)(k0 + kk) * DHEAD + n];
    }
    __syncthreads();
#pragma unroll
    for (int it = 0; it < 16; it++) {
        int idx = tid + it * 256;
        int n = idx >> 6, kk = idx & 63;
        float v = tile[kk][n];
        unsigned short hu = f2bf_hi(v);
        size_t o = (size_t)hp * DHEAD * INDIM + (size_t)n * INDIM + k0 + kk;
        g_wthi[o] = hu; g_wtlo[o] = f2bf_hi(v - bf2f(hu));
    }
}

// ---------------------------------------------------------------------------
// proj_mma: bf16 3-term compute (validated). Epilogue:
//   q -> fp16 hi/lo split, k -> single fp16, v -> fp32 (transposed later).
// ---------------------------------------------------------------------------
#define AHI_OFF 0
#define ALO_OFF (128*72)
#define BHI_OFF (2*128*72)
#define BLO_OFF (2*128*72 + 64*72)
#define PROJ_SMEM_ELEMS (2*128*72 + 2*64*72)

__global__ __launch_bounds__(128)
void proj_mma(const float* __restrict__ bq, const float* __restrict__ bk,
              const float* __restrict__ bv)
{
    extern __shared__ char smem_raw[];
    unsigned short* sb = (unsigned short*)smem_raw;
    const uint32_t sbase = smem_u32(sb);

    const int tid  = threadIdx.x;
    const int wid  = tid >> 5;
    const int lane = tid & 31;
    const int mbase = blockIdx.x * 128;
    const int h     = blockIdx.y;
    const int p     = blockIdx.z;

    const unsigned short* Whi = g_wthi + (size_t)(h * 3 + p) * DHEAD * INDIM;
    const unsigned short* Wlo = g_wtlo + (size_t)(h * 3 + p) * DHEAD * INDIM;

    float acc[2][8][4];
#pragma unroll
    for (int mt = 0; mt < 2; mt++)
#pragma unroll
        for (int nt = 0; nt < 8; nt++)
#pragma unroll
            for (int e = 0; e < 4; e++) acc[mt][nt][e] = 0.f;

    const int mi   = lane >> 3;
    const int l8   = lane & 7;
    const int a_rofs = l8 + (mi & 1) * 8;
    const int a_kofs = (mi >> 1) * 8;
    const int b_nofs = l8 + (mi >> 1) * 8;
    const int b_kofs = (mi & 1) * 8;

    for (int c = 0; c < 16; c++) {
        __syncthreads();
#pragma unroll
        for (int it = 0; it < 8; it++) {
            int idx = tid + it * 128;
            int r = idx >> 3, sg = idx & 7;
            *(uint4*)(sb + AHI_OFF + r * 72 + sg * 8) =
                *(const uint4*)(g_xhi + (size_t)(mbase + r) * INDIM + c * 64 + sg * 8);
            *(uint4*)(sb + ALO_OFF + r * 72 + sg * 8) =
                *(const uint4*)(g_xlo + (size_t)(mbase + r) * INDIM + c * 64 + sg * 8);
        }
#pragma unroll
        for (int it = 0; it < 4; it++) {
            int idx = tid + it * 128;
            int n = idx >> 3, sg = idx & 7;
            *(uint4*)(sb + BHI_OFF + n * 72 + sg * 8) =
                *(const uint4*)(Whi + (size_t)n * INDIM + c * 64 + sg * 8);
            *(uint4*)(sb + BLO_OFF + n * 72 + sg * 8) =
                *(const uint4*)(Wlo + (size_t)n * INDIM + c * 64 + sg * 8);
        }
        __syncthreads();

#pragma unroll
        for (int ks = 0; ks < 4; ks++) {
            const int k0 = ks * 16;
            uint32_t bhi[8][2], blo[8][2];
#pragma unroll
            for (int np = 0; np < 4; np++) {
                int n = np * 16 + b_nofs;
                uint32_t ah = sbase + (uint32_t)(BHI_OFF + n * 72 + k0 + b_kofs) * 2;
                uint32_t al = sbase + (uint32_t)(BLO_OFF + n * 72 + k0 + b_kofs) * 2;
                LDMATRIX_X4(bhi[np*2][0], bhi[np*2][1], bhi[np*2+1][0], bhi[np*2+1][1], ah);
                LDMATRIX_X4(blo[np*2][0], blo[np*2][1], blo[np*2+1][0], blo[np*2+1][1], al);
            }
#pragma unroll
            for (int mt = 0; mt < 2; mt++) {
                int r = wid * 32 + mt * 16 + a_rofs;
                uint32_t ahad = sbase + (uint32_t)(AHI_OFF + r * 72 + k0 + a_kofs) * 2;
                uint32_t alad = sbase + (uint32_t)(ALO_OFF + r * 72 + k0 + a_kofs) * 2;
                uint32_t ah[4], al[4];
                LDMATRIX_X4(ah[0], ah[1], ah[2], ah[3], ahad);
                LDMATRIX_X4(al[0], al[1], al[2], al[3], alad);
#pragma unroll
                for (int nt = 0; nt < 8; nt++) {
                    mma_bf16(acc[mt][nt], ah, bhi[nt]);
                    mma_bf16(acc[mt][nt], ah, blo[nt]);
                    mma_bf16(acc[mt][nt], al, bhi[nt]);
                }
            }
        }
    }

    const float* bias = ((p == 0) ? bq : (p == 1) ? bk : bv) + h * DHEAD;
    const int quad = lane >> 2, pr = lane & 3;

#pragma unroll
    for (int mt = 0; mt < 2; mt++) {
#pragma unroll
        for (int half = 0; half < 2; half++) {
            int tok = mbase + wid * 32 + mt * 16 + quad + half * 8;
            int b = tok >> 11, s = tok & 2047;
            size_t base = ((size_t)(b * NHEADS + h) * SEQ + s) * DHEAD;
            if (p == 0) {
                // q: fp16 split hi/lo
#pragma unroll
                for (int nt = 0; nt < 8; nt++) {
                    int col = nt * 8 + pr * 2;
                    float2 bb = *(const float2*)(bias + col);
                    uint32_t ph, pl;
                    split_pack2_h(acc[mt][nt][half*2 + 0] + bb.x,
                                  acc[mt][nt][half*2 + 1] + bb.y, ph, pl);
                    *(uint32_t*)(g_qhi + base + col) = ph;
                    *(uint32_t*)(g_qlo + base + col) = pl;
                }
            } else if (p == 1) {
                // k: single fp16
#pragma unroll
                for (int nt = 0; nt < 8; nt++) {
                    int col = nt * 8 + pr * 2;
                    float2 bb = *(const float2*)(bias + col);
                    *(uint32_t*)(g_khi + base + col) =
                        pack_h2(acc[mt][nt][half*2 + 0] + bb.x,
                                acc[mt][nt][half*2 + 1] + bb.y);
                }
            } else {
                float* dst = g_v + base;
#pragma unroll
                for (int nt = 0; nt < 8; nt++) {
                    int col = nt * 8 + pr * 2;
                    float2 bb = *(const float2*)(bias + col);
                    float2 v;
                    v.x = acc[mt][nt][half*2 + 0] + bb.x;
                    v.y = acc[mt][nt][half*2 + 1] + bb.y;
                    *(float2*)(dst + col) = v;
                }
            }
        }
    }
}

// ---------------------------------------------------------------------------
// convert_vt: v fp32 [bh][s][d] -> FP16 hi + fp16 residual, [bh][d][s].
// ---------------------------------------------------------------------------
__global__ __launch_bounds__(256)
void convert_vt()
{
    __shared__ float tile[64][65];
    const int s0 = blockIdx.x * 64;
    const int bh = blockIdx.y;
    const int tid = threadIdx.x;
    const float* V = g_v + (size_t)bh * SEQ * DHEAD;

#pragma unroll
    for (int it = 0; it < 16; it++) {
        int idx = tid + it * 256;
        int r = idx >> 6, d = idx & 63;
        tile[r][d] = V[(size_t)(s0 + r) * DHEAD + d];
    }
    __syncthreads();
#pragma unroll
    for (int it = 0; it < 16; it++) {
        int idx = tid + it * 256;
        int d = idx >> 6, cc = idx & 63;
        float v = tile[cc][d];
        unsigned short hu = f2h_raw(v);
        size_t o = (size_t)bh * DHEAD * SEQ + (size_t)d * SEQ + s0 + cc;
        g_vthi[o] = hu; g_vtlo[o] = f2h_raw(v - h2f(hu));
    }
}

// ---------------------------------------------------------------------------
// attn_mma: QK^T = fp16, q-split x single-k (2 MMAs); PV = fp16, single-P x
// split-V (2 MMAs). cp.async 2-stage ring. Per-stage buffer: K | Vhi | Vlo.
// ---------------------------------------------------------------------------
#define TQ_HI 0
#define TQ_LO 4608            // 64*72
#define BUF0  9216            // 2*64*72
#define BUFSZ 13824           // 3*64*72 (K + Vhi + Vlo)
#define ATTN_SMEM_BYTES ((2*4608 + 2*BUFSZ) * 2)   // 73728 B -> 3 CTAs/SM

__device__ __forceinline__ void attn_load_chunk(
    uint32_t sbase, int tid, int kb, int bufbase,
    const unsigned short* Khi,
    const unsigned short* Vthi, const unsigned short* Vtlo)
{
#pragma unroll
    for (int it = 0; it < 4; it++) {            // K (single fp16): 512 slots
        int idx = tid + it * 128;
        int r = idx >> 3, sg = idx & 7;
        const unsigned short* src = Khi + (size_t)(kb + r) * DHEAD + sg * 8;
        uint32_t dst = sbase + (uint32_t)(bufbase + r * 72 + sg * 8) * 2;
        CP_ASYNC16(dst, src);
    }
#pragma unroll
    for (int it = 0; it < 8; it++) {            // Vt hi/lo (fp16): 1024 slots
        int idx  = tid + it * 128;
        int half = idx >> 9;
        int rem  = idx & 511;
        int r    = rem >> 3, sg = rem & 7;      // r = dv row
        const unsigned short* src =
            (half ? Vtlo : Vthi) + (size_t)r * SEQ + kb + sg * 8;
        uint32_t dst = sbase + (uint32_t)(bufbase + (1 + half) * 4608 + r * 72 + sg * 8) * 2;
        CP_ASYNC16(dst, src);
    }
    CP_COMMIT();
}

__global__ __launch_bounds__(128)
void attn_mma(float* __restrict__ out)
{
    extern __shared__ char smem_raw[];
    unsigned short* sb = (unsigned short*)smem_raw;
    const uint32_t sbase = smem_u32(sb);

    const int tid  = threadIdx.x;
    const int wq   = tid >> 5;
    const int lane = tid & 31;
    const int quad = lane >> 2, pr = lane & 3;
    const int mi   = lane >> 3, l8 = lane & 7;
    const int a_rofs = l8 + (mi & 1) * 8;
    const int a_kofs = (mi >> 1) * 8;
    const int b_nofs = l8 + (mi >> 1) * 8;
    const int b_kofs = (mi & 1) * 8;

    const int qbase = blockIdx.x * 64;
    const int bh    = blockIdx.y;

    const unsigned short* Qhi = g_qhi + (size_t)bh * SEQ * DHEAD;
    const unsigned short* Qlo = g_qlo + (size_t)bh * SEQ * DHEAD;
    const unsigned short* Khi = g_khi + (size_t)bh * SEQ * DHEAD;
    const unsigned short* Vthi = g_vthi + (size_t)bh * DHEAD * SEQ;
    const unsigned short* Vtlo = g_vtlo + (size_t)bh * DHEAD * SEQ;

    // prologue: Q tile (hi/lo fp16) + chunk 0
#pragma unroll
    for (int it = 0; it < 8; it++) {
        int idx  = tid + it * 128;
        int half = idx >> 9;
        int rem  = idx & 511;
        int r    = rem >> 3, sg = rem & 7;
        const unsigned short* src =
            (half ? Qlo : Qhi) + (size_t)(qbase + r) * DHEAD + sg * 8;
        uint32_t dst = sbase + (uint32_t)((half ? TQ_LO : TQ_HI) + r * 72 + sg * 8) * 2;
        CP_ASYNC16(dst, src);
    }
    attn_load_chunk(sbase, tid, 0, BUF0, Khi, Vthi, Vtlo);

    float oacc[8][4];
    float mrow[2] = {-1e30f, -1e30f}, lrow[2] = {0.f, 0.f};
#pragma unroll
    for (int nt = 0; nt < 8; nt++)
#pragma unroll
        for (int e = 0; e < 4; e++) oacc[nt][e] = 0.f;

    const int NCHUNK = SEQ / 64;
    for (int i = 0; i < NCHUNK; i++) {
        CP_WAIT0();
        __syncthreads();
        if (i + 1 < NCHUNK)
            attn_load_chunk(sbase, tid, (i + 1) * 64,
                            BUF0 + ((i + 1) & 1) * BUFSZ, Khi, Vthi, Vtlo);

        const int Bb   = BUF0 + (i & 1) * BUFSZ;
        const int TK   = Bb;
        const int TVHI = Bb + 4608, TVLO = Bb + 9216;

        // ---- QK^T (fp16): q hi/lo split x single k, 2 MMAs per n-tile ----
        float c[8][4];
#pragma unroll
        for (int nt = 0; nt < 8; nt++)
#pragma unroll
            for (int e = 0; e < 4; e++) c[nt][e] = 0.f;

#pragma unroll
        for (int ks = 0; ks < 4; ks++) {
            const int k0 = ks * 16;
            uint32_t qh[4], ql[4];
            {
                int r = wq * 16 + a_rofs;
                LDMATRIX_X4(qh[0], qh[1], qh[2], qh[3],
                            sbase + (uint32_t)(TQ_HI + r * 72 + k0 + a_kofs) * 2);
                LDMATRIX_X4(ql[0], ql[1], ql[2], ql[3],
                            sbase + (uint32_t)(TQ_LO + r * 72 + k0 + a_kofs) * 2);
            }
#pragma unroll
            for (int np = 0; np < 4; np++) {
                int n = np * 16 + b_nofs;
                uint32_t kh[4];
                LDMATRIX_X4(kh[0], kh[1], kh[2], kh[3],
                            sbase + (uint32_t)(TK + n * 72 + k0 + b_kofs) * 2);
                uint32_t b0h[2] = {kh[0], kh[1]}, b1h[2] = {kh[2], kh[3]};
                mma_f16(c[np*2],   qh, b0h);
                mma_f16(c[np*2],   ql, b0h);
                mma_f16(c[np*2+1], qh, b1h);
                mma_f16(c[np*2+1], ql, b1h);
            }
        }

        // ---- online softmax (rows quad / quad+8; 4 lanes per row) ----
#pragma unroll
        for (int r = 0; r < 2; r++) {
            const int e = r * 2;
            float mx = c[0][e];
#pragma unroll
            for (int nt = 0; nt < 8; nt++)
                mx = fmaxf(mx, fmaxf(c[nt][e], c[nt][e+1]));
            mx = fmaxf(mx, __shfl_xor_sync(0xffffffffu, mx, 1));
            mx = fmaxf(mx, __shfl_xor_sync(0xffffffffu, mx, 2));
            float mnew  = fmaxf(mrow[r], mx);
            float alpha = __expf(mrow[r] - mnew);
            float ps = 0.f;
#pragma unroll
            for (int nt = 0; nt < 8; nt++) {
                c[nt][e]   = __expf(c[nt][e]   - mnew);
                c[nt][e+1] = __expf(c[nt][e+1] - mnew);
                ps += c[nt][e] + c[nt][e+1];
            }
            ps += __shfl_xor_sync(0xffffffffu, ps, 1);
            ps += __shfl_xor_sync(0xffffffffu, ps, 2);
            lrow[r] = lrow[r] * alpha + ps;
            mrow[r] = mnew;
#pragma unroll
            for (int nt = 0; nt < 8; nt++) {
                oacc[nt][e]   *= alpha;
                oacc[nt][e+1] *= alpha;
            }
        }

        // ---- PV (fp16): single-P fragments x split-V, 2 MMAs per n-tile ----
#pragma unroll
        for (int ks = 0; ks < 4; ks++) {
            uint32_t ph[4];
            ph[0] = pack_h2(c[2*ks][0],   c[2*ks][1]);
            ph[1] = pack_h2(c[2*ks][2],   c[2*ks][3]);
            ph[2] = pack_h2(c[2*ks+1][0], c[2*ks+1][1]);
            ph[3] = pack_h2(c[2*ks+1][2], c[2*ks+1][3]);
#pragma unroll
            for (int np = 0; np < 4; np++) {
                int n = np * 16 + b_nofs;
                uint32_t vh[4], vl[4];
                LDMATRIX_X4(vh[0], vh[1], vh[2], vh[3],
                            sbase + (uint32_t)(TVHI + n * 72 + ks * 16 + b_kofs) * 2);
                LDMATRIX_X4(vl[0], vl[1], vl[2], vl[3],
                            sbase + (uint32_t)(TVLO + n * 72 + ks * 16 + b_kofs) * 2);
                uint32_t b0h[2] = {vh[0], vh[1]}, b1h[2] = {vh[2], vh[3]};
                uint32_t b0l[2] = {vl[0], vl[1]}, b1l[2] = {vl[2], vl[3]};
                mma_f16(oacc[np*2],   ph, b0h);
                mma_f16(oacc[np*2],   ph, b0l);
                mma_f16(oacc[np*2+1], ph, b1h);
                mma_f16(oacc[np*2+1], ph, b1l);
            }
        }
    }

    // ---- epilogue: out[b][s][h*64+dv] = oacc / (l * 8) ----
    const int b = bh >> 4, h = bh & 15;
#pragma unroll
    for (int half = 0; half < 2; half++) {
        int srow = qbase + wq * 16 + quad + half * 8;
        float inv = 1.0f / (lrow[half] * 8.0f);
        float* dst = out + ((size_t)(b * SEQ + srow)) * (NHEADS * DHEAD) + h * DHEAD;
#pragma unroll
        for (int nt = 0; nt < 8; nt++) {
            int col = nt * 8 + pr * 2;
            float2 v;
            v.x = oacc[nt][half*2 + 0] * inv;
            v.y = oacc[nt][half*2 + 1] * inv;
            *(float2*)(dst + col) = v;
        }
    }
}

// ---------------------------------------------------------------------------
extern "C" void kernel_launch(void* const* d_in, const int* in_sizes, int n_in,
                              void* d_out, int out_size)
{
    const float* x  = (const float*)d_in[0];
    const float* Wq = (const float*)d_in[1];
    const float* bq = (const float*)d_in[2];
    const float* Wk = (const float*)d_in[3];
    const float* bk = (const float*)d_in[4];
    const float* Wv = (const float*)d_in[5];
    const float* bv = (const float*)d_in[6];
    float* out = (float*)d_out;

    cudaFuncSetAttribute(proj_mma, cudaFuncAttributeMaxDynamicSharedMemorySize,
                         PROJ_SMEM_ELEMS * 2);
    cudaFuncSetAttribute(attn_mma, cudaFuncAttributeMaxDynamicSharedMemorySize,
                         ATTN_SMEM_BYTES);

    convert_x<<<(NTOK * INDIM / 4) / 256, 256>>>(x);
    convert_w<<<dim3(INDIM / 64, NHEADS * 3), 256>>>(Wq, Wk, Wv);
    proj_mma<<<dim3(NTOK / 128, NHEADS, 3), 128, PROJ_SMEM_ELEMS * 2>>>(bq, bk, bv);
    convert_vt<<<dim3(SEQ / 64, BH), 256>>>();
    attn_mma<<<dim3(SEQ / 64, BH), 128, ATTN_SMEM_BYTES>>>(out);
}

// round 16
// speedup vs baseline: 4.3188x; 1.1147x over previous
#include <cuda_runtime.h>
#include <cuda_bf16.h>
#include <stdint.h>
#include <math.h>

#define NHEADS 16
#define INDIM  1024
#define DHEAD  64
#define BATCH  2
#define SEQ    2048
#define NTOK   (BATCH*SEQ)
#define BH     (BATCH*NHEADS)

// fp32 V scratch (needed for the transpose pass), layout [B*H][S][DHEAD]
__device__ float g_v[(size_t)BH*SEQ*DHEAD];

// Split-precision inputs for bf16 tensor-core MMA (raw u16 payloads).
__device__ unsigned short g_xhi[(size_t)NTOK*INDIM];
__device__ unsigned short g_xlo[(size_t)NTOK*INDIM];
__device__ unsigned short g_wthi[(size_t)NHEADS*3*DHEAD*INDIM];
__device__ unsigned short g_wtlo[(size_t)NHEADS*3*DHEAD*INDIM];

// Attention operands: q fp16 hi/lo split, k single fp16 ([bh][s][d]);
// v transposed single fp16 ([bh][d][s]).
__device__ unsigned short g_qhi[(size_t)BH*SEQ*DHEAD];
__device__ unsigned short g_qlo[(size_t)BH*SEQ*DHEAD];
__device__ unsigned short g_khi[(size_t)BH*SEQ*DHEAD];
__device__ unsigned short g_vthi[(size_t)BH*DHEAD*SEQ];

__device__ __forceinline__ uint32_t smem_u32(const void* p) {
    uint32_t a;
    asm("{ .reg .u64 t; cvta.to.shared.u64 t, %1; cvt.u32.u64 %0, t; }"
        : "=r"(a) : "l"(p));
    return a;
}

__device__ __forceinline__ unsigned short f2bf_hi(float f) {
    __nv_bfloat16 h = __float2bfloat16(f);
    __nv_bfloat16_raw r = *(__nv_bfloat16_raw*)&h;
    return r.x;
}
__device__ __forceinline__ float bf2f(unsigned short u) {
    return __uint_as_float((uint32_t)u << 16);
}
// fp16 conversions via bare PTX (no cuda_fp16.h dependency)
__device__ __forceinline__ unsigned short f2h_raw(float f) {
    unsigned short r;
    asm("cvt.rn.f16.f32 %0, %1;" : "=h"(r) : "f"(f));
    return r;
}
__device__ __forceinline__ float h2f(unsigned short u) {
    float f;
    asm("cvt.f32.f16 %0, %1;" : "=f"(f) : "h"(u));
    return f;
}
// pack two floats to fp16x2 (lo = x, hi = y) in one cvt
__device__ __forceinline__ uint32_t pack_h2(float x, float y) {
    uint32_t r;
    asm("cvt.rn.f16x2.f32 %0, %1, %2;" : "=r"(r) : "f"(y), "f"(x));
    return r;
}

// split (x,y) -> fp16 hi-pair and fp16 residual-pair (lower 16 bits = x)
__device__ __forceinline__ void split_pack2_h(float x, float y,
                                              uint32_t& hi, uint32_t& lo) {
    unsigned short hx = f2h_raw(x), hy = f2h_raw(y);
    float rx = x - h2f(hx);
    float ry = y - h2f(hy);
    hi = (uint32_t)hx | ((uint32_t)hy << 16);
    lo = (uint32_t)f2h_raw(rx) | ((uint32_t)f2h_raw(ry) << 16);
}

// bf16 mma: D(f32) = A(bf16,row) x B(bf16,col) + C, m16n8k16.
__device__ __forceinline__ void mma_bf16(float* c, const uint32_t* a,
                                         const uint32_t* b) {
    float d0, d1, d2, d3;
    asm volatile(
        "mma.sync.aligned.m16n8k16.row.col.f32.bf16.bf16.f32 "
        "{%0,%1,%2,%3}, {%4,%5,%6,%7}, {%8,%9}, {%10,%11,%12,%13};"
        : "=f"(d0), "=f"(d1), "=f"(d2), "=f"(d3)
        : "r"(a[0]), "r"(a[1]), "r"(a[2]), "r"(a[3]),
          "r"(b[0]), "r"(b[1]),
          "f"(c[0]), "f"(c[1]), "f"(c[2]), "f"(c[3]));
    c[0] = d0; c[1] = d1; c[2] = d2; c[3] = d3;
}

// fp16 mma: D(f32) = A(f16,row) x B(f16,col) + C, m16n8k16.
__device__ __forceinline__ void mma_f16(float* c, const uint32_t* a,
                                        const uint32_t* b) {
    float d0, d1, d2, d3;
    asm volatile(
        "mma.sync.aligned.m16n8k16.row.col.f32.f16.f16.f32 "
        "{%0,%1,%2,%3}, {%4,%5,%6,%7}, {%8,%9}, {%10,%11,%12,%13};"
        : "=f"(d0), "=f"(d1), "=f"(d2), "=f"(d3)
        : "r"(a[0]), "r"(a[1]), "r"(a[2]), "r"(a[3]),
          "r"(b[0]), "r"(b[1]),
          "f"(c[0]), "f"(c[1]), "f"(c[2]), "f"(c[3]));
    c[0] = d0; c[1] = d1; c[2] = d2; c[3] = d3;
}

#define LDMATRIX_X4(r0, r1, r2, r3, addr)                                      \
    asm volatile("ldmatrix.sync.aligned.m8n8.x4.shared.b16 {%0,%1,%2,%3}, [%4];" \
                 : "=r"(r0), "=r"(r1), "=r"(r2), "=r"(r3) : "r"(addr))

#define CP_ASYNC16(smem_addr, gptr)                                            \
    asm volatile("cp.async.cg.shared.global [%0], [%1], 16;"                   \
                 :: "r"(smem_addr), "l"(gptr) : "memory")
#define CP_COMMIT()  asm volatile("cp.async.commit_group;" ::: "memory")
#define CP_WAIT0()   asm volatile("cp.async.wait_group 0;" ::: "memory")

// ---------------------------------------------------------------------------
__global__ __launch_bounds__(256)
void convert_x(const float* __restrict__ x)
{
    int i = blockIdx.x * 256 + threadIdx.x;
    float4 v = ((const float4*)x)[i];
    float f[4] = {v.x, v.y, v.z, v.w};
    ushort4 hh, ll;
    unsigned short* hp = (unsigned short*)&hh;
    unsigned short* lp = (unsigned short*)&ll;
#pragma unroll
    for (int j = 0; j < 4; j++) {
        unsigned short hu = f2bf_hi(f[j]);
        hp[j] = hu; lp[j] = f2bf_hi(f[j] - bf2f(hu));
    }
    ((ushort4*)g_xhi)[i] = hh;
    ((ushort4*)g_xlo)[i] = ll;
}

// ---------------------------------------------------------------------------
__global__ __launch_bounds__(256)
void convert_w(const float* __restrict__ Wq, const float* __restrict__ Wk,
               const float* __restrict__ Wv)
{
    __shared__ float tile[64][65];
    const int k0 = blockIdx.x * 64;
    const int hp = blockIdx.y;
    const int h  = hp / 3, p = hp % 3;
    const float* W = ((p == 0) ? Wq : (p == 1) ? Wk : Wv) + (size_t)h * INDIM * DHEAD;
    const int tid = threadIdx.x;

#pragma unroll
    for (int it = 0; it < 16; it++) {
        int idx = tid + it * 256;
        int kk = idx >> 6, n = idx & 63;
        tile[kk][n] = W[(size_t)(k0 + kk) * DHEAD + n];
    }
    __syncthreads();
#pragma unroll
    for (int it = 0; it < 16; it++) {
        int idx = tid + it * 256;
        int n = idx >> 6, kk = idx & 63;
        float v = tile[kk][n];
        unsigned short hu = f2bf_hi(v);
        size_t o = (size_t)hp * DHEAD * INDIM + (size_t)n * INDIM + k0 + kk;
        g_wthi[o] = hu; g_wtlo[o] = f2bf_hi(v - bf2f(hu));
    }
}

// ---------------------------------------------------------------------------
// proj_mma: bf16 3-term compute (validated). Epilogue:
//   q -> fp16 hi/lo split, k -> single fp16, v -> fp32 (transposed later).
// ---------------------------------------------------------------------------
#define AHI_OFF 0
#define ALO_OFF (128*72)
#define BHI_OFF (2*128*72)
#define BLO_OFF (2*128*72 + 64*72)
#define PROJ_SMEM_ELEMS (2*128*72 + 2*64*72)

__global__ __launch_bounds__(128)
void proj_mma(const float* __restrict__ bq, const float* __restrict__ bk,
              const float* __restrict__ bv)
{
    extern __shared__ char smem_raw[];
    unsigned short* sb = (unsigned short*)smem_raw;
    const uint32_t sbase = smem_u32(sb);

    const int tid  = threadIdx.x;
    const int wid  = tid >> 5;
    const int lane = tid & 31;
    const int mbase = blockIdx.x * 128;
    const int h     = blockIdx.y;
    const int p     = blockIdx.z;

    const unsigned short* Whi = g_wthi + (size_t)(h * 3 + p) * DHEAD * INDIM;
    const unsigned short* Wlo = g_wtlo + (size_t)(h * 3 + p) * DHEAD * INDIM;

    float acc[2][8][4];
#pragma unroll
    for (int mt = 0; mt < 2; mt++)
#pragma unroll
        for (int nt = 0; nt < 8; nt++)
#pragma unroll
            for (int e = 0; e < 4; e++) acc[mt][nt][e] = 0.f;

    const int mi   = lane >> 3;
    const int l8   = lane & 7;
    const int a_rofs = l8 + (mi & 1) * 8;
    const int a_kofs = (mi >> 1) * 8;
    const int b_nofs = l8 + (mi >> 1) * 8;
    const int b_kofs = (mi & 1) * 8;

    for (int c = 0; c < 16; c++) {
        __syncthreads();
#pragma unroll
        for (int it = 0; it < 8; it++) {
            int idx = tid + it * 128;
            int r = idx >> 3, sg = idx & 7;
            *(uint4*)(sb + AHI_OFF + r * 72 + sg * 8) =
                *(const uint4*)(g_xhi + (size_t)(mbase + r) * INDIM + c * 64 + sg * 8);
            *(uint4*)(sb + ALO_OFF + r * 72 + sg * 8) =
                *(const uint4*)(g_xlo + (size_t)(mbase + r) * INDIM + c * 64 + sg * 8);
        }
#pragma unroll
        for (int it = 0; it < 4; it++) {
            int idx = tid + it * 128;
            int n = idx >> 3, sg = idx & 7;
            *(uint4*)(sb + BHI_OFF + n * 72 + sg * 8) =
                *(const uint4*)(Whi + (size_t)n * INDIM + c * 64 + sg * 8);
            *(uint4*)(sb + BLO_OFF + n * 72 + sg * 8) =
                *(const uint4*)(Wlo + (size_t)n * INDIM + c * 64 + sg * 8);
        }
        __syncthreads();

#pragma unroll
        for (int ks = 0; ks < 4; ks++) {
            const int k0 = ks * 16;
            uint32_t bhi[8][2], blo[8][2];
#pragma unroll
            for (int np = 0; np < 4; np++) {
                int n = np * 16 + b_nofs;
                uint32_t ah = sbase + (uint32_t)(BHI_OFF + n * 72 + k0 + b_kofs) * 2;
                uint32_t al = sbase + (uint32_t)(BLO_OFF + n * 72 + k0 + b_kofs) * 2;
                LDMATRIX_X4(bhi[np*2][0], bhi[np*2][1], bhi[np*2+1][0], bhi[np*2+1][1], ah);
                LDMATRIX_X4(blo[np*2][0], blo[np*2][1], blo[np*2+1][0], blo[np*2+1][1], al);
            }
#pragma unroll
            for (int mt = 0; mt < 2; mt++) {
                int r = wid * 32 + mt * 16 + a_rofs;
                uint32_t ahad = sbase + (uint32_t)(AHI_OFF + r * 72 + k0 + a_kofs) * 2;
                uint32_t alad = sbase + (uint32_t)(ALO_OFF + r * 72 + k0 + a_kofs) * 2;
                uint32_t ah[4], al[4];
                LDMATRIX_X4(ah[0], ah[1], ah[2], ah[3], ahad);
                LDMATRIX_X4(al[0], al[1], al[2], al[3], alad);
#pragma unroll
                for (int nt = 0; nt < 8; nt++) {
                    mma_bf16(acc[mt][nt], ah, bhi[nt]);
                    mma_bf16(acc[mt][nt], ah, blo[nt]);
                    mma_bf16(acc[mt][nt], al, bhi[nt]);
                }
            }
        }
    }

    const float* bias = ((p == 0) ? bq : (p == 1) ? bk : bv) + h * DHEAD;
    const int quad = lane >> 2, pr = lane & 3;

#pragma unroll
    for (int mt = 0; mt < 2; mt++) {
#pragma unroll
        for (int half = 0; half < 2; half++) {
            int tok = mbase + wid * 32 + mt * 16 + quad + half * 8;
            int b = tok >> 11, s = tok & 2047;
            size_t base = ((size_t)(b * NHEADS + h) * SEQ + s) * DHEAD;
            if (p == 0) {
                // q: fp16 split hi/lo
#pragma unroll
                for (int nt = 0; nt < 8; nt++) {
                    int col = nt * 8 + pr * 2;
                    float2 bb = *(const float2*)(bias + col);
                    uint32_t ph, pl;
                    split_pack2_h(acc[mt][nt][half*2 + 0] + bb.x,
                                  acc[mt][nt][half*2 + 1] + bb.y, ph, pl);
                    *(uint32_t*)(g_qhi + base + col) = ph;
                    *(uint32_t*)(g_qlo + base + col) = pl;
                }
            } else if (p == 1) {
                // k: single fp16
#pragma unroll
                for (int nt = 0; nt < 8; nt++) {
                    int col = nt * 8 + pr * 2;
                    float2 bb = *(const float2*)(bias + col);
                    *(uint32_t*)(g_khi + base + col) =
                        pack_h2(acc[mt][nt][half*2 + 0] + bb.x,
                                acc[mt][nt][half*2 + 1] + bb.y);
                }
            } else {
                float* dst = g_v + base;
#pragma unroll
                for (int nt = 0; nt < 8; nt++) {
                    int col = nt * 8 + pr * 2;
                    float2 bb = *(const float2*)(bias + col);
                    float2 v;
                    v.x = acc[mt][nt][half*2 + 0] + bb.x;
                    v.y = acc[mt][nt][half*2 + 1] + bb.y;
                    *(float2*)(dst + col) = v;
                }
            }
        }
    }
}

// ---------------------------------------------------------------------------
// convert_vt: v fp32 [bh][s][d] -> single FP16, [bh][d][s].
// ---------------------------------------------------------------------------
__global__ __launch_bounds__(256)
void convert_vt()
{
    __shared__ float tile[64][65];
    const int s0 = blockIdx.x * 64;
    const int bh = blockIdx.y;
    const int tid = threadIdx.x;
    const float* V = g_v + (size_t)bh * SEQ * DHEAD;

#pragma unroll
    for (int it = 0; it < 16; it++) {
        int idx = tid + it * 256;
        int r = idx >> 6, d = idx & 63;
        tile[r][d] = V[(size_t)(s0 + r) * DHEAD + d];
    }
    __syncthreads();
#pragma unroll
    for (int it = 0; it < 16; it++) {
        int idx = tid + it * 256;
        int d = idx >> 6, cc = idx & 63;
        size_t o = (size_t)bh * DHEAD * SEQ + (size_t)d * SEQ + s0 + cc;
        g_vthi[o] = f2h_raw(tile[cc][d]);
    }
}

// ---------------------------------------------------------------------------
// attn_mma: QK^T = fp16, q-split x single-k (2 MMAs); PV = fp16, single-P x
// single-V (1 MMA). cp.async 2-stage ring. Per-stage buffer: K | V.
// ---------------------------------------------------------------------------
#define TQ_HI 0
#define TQ_LO 4608            // 64*72
#define BUF0  9216            // 2*64*72
#define BUFSZ 9216            // 2*64*72 (K + V)
#define ATTN_SMEM_BYTES ((2*4608 + 2*BUFSZ) * 2)   // 55296 B -> 4 CTAs/SM

__device__ __forceinline__ void attn_load_chunk(
    uint32_t sbase, int tid, int kb, int bufbase,
    const unsigned short* Khi, const unsigned short* Vthi)
{
#pragma unroll
    for (int it = 0; it < 4; it++) {            // K (single fp16): 512 slots
        int idx = tid + it * 128;
        int r = idx >> 3, sg = idx & 7;
        const unsigned short* src = Khi + (size_t)(kb + r) * DHEAD + sg * 8;
        uint32_t dst = sbase + (uint32_t)(bufbase + r * 72 + sg * 8) * 2;
        CP_ASYNC16(dst, src);
    }
#pragma unroll
    for (int it = 0; it < 4; it++) {            // Vt (single fp16): 512 slots
        int idx = tid + it * 128;
        int r = idx >> 3, sg = idx & 7;         // r = dv row
        const unsigned short* src = Vthi + (size_t)r * SEQ + kb + sg * 8;
        uint32_t dst = sbase + (uint32_t)(bufbase + 4608 + r * 72 + sg * 8) * 2;
        CP_ASYNC16(dst, src);
    }
    CP_COMMIT();
}

__global__ __launch_bounds__(128)
void attn_mma(float* __restrict__ out)
{
    extern __shared__ char smem_raw[];
    unsigned short* sb = (unsigned short*)smem_raw;
    const uint32_t sbase = smem_u32(sb);

    const int tid  = threadIdx.x;
    const int wq   = tid >> 5;
    const int lane = tid & 31;
    const int quad = lane >> 2, pr = lane & 3;
    const int mi   = lane >> 3, l8 = lane & 7;
    const int a_rofs = l8 + (mi & 1) * 8;
    const int a_kofs = (mi >> 1) * 8;
    const int b_nofs = l8 + (mi >> 1) * 8;
    const int b_kofs = (mi & 1) * 8;

    const int qbase = blockIdx.x * 64;
    const int bh    = blockIdx.y;

    const unsigned short* Qhi = g_qhi + (size_t)bh * SEQ * DHEAD;
    const unsigned short* Qlo = g_qlo + (size_t)bh * SEQ * DHEAD;
    const unsigned short* Khi = g_khi + (size_t)bh * SEQ * DHEAD;
    const unsigned short* Vthi = g_vthi + (size_t)bh * DHEAD * SEQ;

    // prologue: Q tile (hi/lo fp16) + chunk 0
#pragma unroll
    for (int it = 0; it < 8; it++) {
        int idx  = tid + it * 128;
        int half = idx >> 9;
        int rem  = idx & 511;
        int r    = rem >> 3, sg = rem & 7;
        const unsigned short* src =
            (half ? Qlo : Qhi) + (size_t)(qbase + r) * DHEAD + sg * 8;
        uint32_t dst = sbase + (uint32_t)((half ? TQ_LO : TQ_HI) + r * 72 + sg * 8) * 2;
        CP_ASYNC16(dst, src);
    }
    attn_load_chunk(sbase, tid, 0, BUF0, Khi, Vthi);

    float oacc[8][4];
    float mrow[2] = {-1e30f, -1e30f}, lrow[2] = {0.f, 0.f};
#pragma unroll
    for (int nt = 0; nt < 8; nt++)
#pragma unroll
        for (int e = 0; e < 4; e++) oacc[nt][e] = 0.f;

    const int NCHUNK = SEQ / 64;
    for (int i = 0; i < NCHUNK; i++) {
        CP_WAIT0();
        __syncthreads();
        if (i + 1 < NCHUNK)
            attn_load_chunk(sbase, tid, (i + 1) * 64,
                            BUF0 + ((i + 1) & 1) * BUFSZ, Khi, Vthi);

        const int Bb = BUF0 + (i & 1) * BUFSZ;
        const int TK = Bb;
        const int TV = Bb + 4608;

        // ---- QK^T (fp16): q hi/lo split x single k, 2 MMAs per n-tile ----
        float c[8][4];
#pragma unroll
        for (int nt = 0; nt < 8; nt++)
#pragma unroll
            for (int e = 0; e < 4; e++) c[nt][e] = 0.f;

#pragma unroll
        for (int ks = 0; ks < 4; ks++) {
            const int k0 = ks * 16;
            uint32_t qh[4], ql[4];
            {
                int r = wq * 16 + a_rofs;
                LDMATRIX_X4(qh[0], qh[1], qh[2], qh[3],
                            sbase + (uint32_t)(TQ_HI + r * 72 + k0 + a_kofs) * 2);
                LDMATRIX_X4(ql[0], ql[1], ql[2], ql[3],
                            sbase + (uint32_t)(TQ_LO + r * 72 + k0 + a_kofs) * 2);
            }
#pragma unroll
            for (int np = 0; np < 4; np++) {
                int n = np * 16 + b_nofs;
                uint32_t kh[4];
                LDMATRIX_X4(kh[0], kh[1], kh[2], kh[3],
                            sbase + (uint32_t)(TK + n * 72 + k0 + b_kofs) * 2);
                uint32_t b0h[2] = {kh[0], kh[1]}, b1h[2] = {kh[2], kh[3]};
                mma_f16(c[np*2],   qh, b0h);
                mma_f16(c[np*2],   ql, b0h);
                mma_f16(c[np*2+1], qh, b1h);
                mma_f16(c[np*2+1], ql, b1h);
            }
        }

        // ---- online softmax (rows quad / quad+8; 4 lanes per row) ----
#pragma unroll
        for (int r = 0; r < 2; r++) {
            const int e = r * 2;
            float mx = c[0][e];
#pragma unroll
            for (int nt = 0; nt < 8; nt++)
                mx = fmaxf(mx, fmaxf(c[nt][e], c[nt][e+1]));
            mx = fmaxf(mx, __shfl_xor_sync(0xffffffffu, mx, 1));
            mx = fmaxf(mx, __shfl_xor_sync(0xffffffffu, mx, 2));
            float mnew  = fmaxf(mrow[r], mx);
            float alpha = __expf(mrow[r] - mnew);
            float ps = 0.f;
#pragma unroll
            for (int nt = 0; nt < 8; nt++) {
                c[nt][e]   = __expf(c[nt][e]   - mnew);
                c[nt][e+1] = __expf(c[nt][e+1] - mnew);
                ps += c[nt][e] + c[nt][e+1];
            }
            ps += __shfl_xor_sync(0xffffffffu, ps, 1);
            ps += __shfl_xor_sync(0xffffffffu, ps, 2);
            lrow[r] = lrow[r] * alpha + ps;
            mrow[r] = mnew;
#pragma unroll
            for (int nt = 0; nt < 8; nt++) {
                oacc[nt][e]   *= alpha;
                oacc[nt][e+1] *= alpha;
            }
        }

        // ---- PV (fp16): single-P x single-V, 1 MMA per n-tile ----
#pragma unroll
        for (int ks = 0; ks < 4; ks++) {
            uint32_t ph[4];
            ph[0] = pack_h2(c[2*ks][0],   c[2*ks][1]);
            ph[1] = pack_h2(c[2*ks][2],   c[2*ks][3]);
            ph[2] = pack_h2(c[2*ks+1][0], c[2*ks+1][1]);
            ph[3] = pack_h2(c[2*ks+1][2], c[2*ks+1][3]);
#pragma unroll
            for (int np = 0; np < 4; np++) {
                int n = np * 16 + b_nofs;
                uint32_t vh[4];
                LDMATRIX_X4(vh[0], vh[1], vh[2], vh[3],
                            sbase + (uint32_t)(TV + n * 72 + ks * 16 + b_kofs) * 2);
                uint32_t b0h[2] = {vh[0], vh[1]}, b1h[2] = {vh[2], vh[3]};
                mma_f16(oacc[np*2],   ph, b0h);
                mma_f16(oacc[np*2+1], ph, b1h);
            }
        }
    }

    // ---- epilogue: out[b][s][h*64+dv] = oacc / (l * 8) ----
    const int b = bh >> 4, h = bh & 15;
#pragma unroll
    for (int half = 0; half < 2; half++) {
        int srow = qbase + wq * 16 + quad + half * 8;
        float inv = 1.0f / (lrow[half] * 8.0f);
        float* dst = out + ((size_t)(b * SEQ + srow)) * (NHEADS * DHEAD) + h * DHEAD;
#pragma unroll
        for (int nt = 0; nt < 8; nt++) {
            int col = nt * 8 + pr * 2;
            float2 v;
            v.x = oacc[nt][half*2 + 0] * inv;
            v.y = oacc[nt][half*2 + 1] * inv;
            *(float2*)(dst + col) = v;
        }
    }
}

// ---------------------------------------------------------------------------
extern "C" void kernel_launch(void* const* d_in, const int* in_sizes, int n_in,
                              void* d_out, int out_size)
{
    const float* x  = (const float*)d_in[0];
    const float* Wq = (const float*)d_in[1];
    const float* bq = (const float*)d_in[2];
    const float* Wk = (const float*)d_in[3];
    const float* bk = (const float*)d_in[4];
    const float* Wv = (const float*)d_in[5];
    const float* bv = (const float*)d_in[6];
    float* out = (float*)d_out;

    cudaFuncSetAttribute(proj_mma, cudaFuncAttributeMaxDynamicSharedMemorySize,
                         PROJ_SMEM_ELEMS * 2);
    cudaFuncSetAttribute(attn_mma, cudaFuncAttributeMaxDynamicSharedMemorySize,
                         ATTN_SMEM_BYTES);

    convert_x<<<(NTOK * INDIM / 4) / 256, 256>>>(x);
    convert_w<<<dim3(INDIM / 64, NHEADS * 3), 256>>>(Wq, Wk, Wv);
    proj_mma<<<dim3(NTOK / 128, NHEADS, 3), 128, PROJ_SMEM_ELEMS * 2>>>(bq, bk, bv);
    convert_vt<<<dim3(SEQ / 64, BH), 256>>>();
    attn_mma<<<dim3(SEQ / 64, BH), 128, ATTN_SMEM_BYTES>>>(out);
}